// round 1
// baseline (speedup 1.0000x reference)
#include <cuda_runtime.h>

#define BB 4
#define CCH 256
#define HH 48
#define NN 2304
#define NHEADS 8
#define DHD 32
#define INNER 256
#define HID 128
#define ATT_SCALE 0.17677669529663687f
#define EPSV 1e-6f

// ---------------- scratch (device globals; no allocation allowed) ----------------
__device__ float g_luma[BB * NN];
__device__ float g_bias[BB * NN];
__device__ float g_h1[BB * HID * NN];
__device__ float g_hm[BB * HID];
__device__ float g_gq[BB * INNER];
__device__ float g_fbq[BB * INNER];
__device__ float g_gk[BB * INNER];
__device__ float g_fbk[BB * INNER];
__device__ float g_gv[BB * INNER];
__device__ float g_fbv[BB * INNER];
__device__ float g_q[BB * INNER * NN];
__device__ float g_k[BB * INNER * NN];
__device__ float g_v[BB * INNER * NN];
__device__ float g_O[BB * INNER * NN];

// ---------------- K1: luma + normalization + pooled bias ----------------
__global__ void luma_kernel(const float* __restrict__ rgb, const float* __restrict__ alphap) {
    __shared__ float sPad[50 * 50];
    __shared__ float red[256];
    int b = blockIdx.x;
    int t = threadIdx.x;
    for (int i = t; i < 2500; i += 256) sPad[i] = 0.f;

    const float* rp = rgb + b * 3 * NN;
    float y[9];
    float mn = 1e30f, mx = -1e30f;
#pragma unroll
    for (int k = 0; k < 9; k++) {
        int p = t + k * 256;
        float yy = 0.299f * rp[p] + 0.587f * rp[NN + p] + 0.114f * rp[2 * NN + p];
        y[k] = yy;
        mn = fminf(mn, yy);
        mx = fmaxf(mx, yy);
    }
    red[t] = mn; __syncthreads();
    for (int s = 128; s > 0; s >>= 1) { if (t < s) red[t] = fminf(red[t], red[t + s]); __syncthreads(); }
    mn = red[0]; __syncthreads();
    red[t] = mx; __syncthreads();
    for (int s = 128; s > 0; s >>= 1) { if (t < s) red[t] = fmaxf(red[t], red[t + s]); __syncthreads(); }
    mx = red[0]; __syncthreads();

    float inv = 1.f / (mx - mn + EPSV);
#pragma unroll
    for (int k = 0; k < 9; k++) {
        int p = t + k * 256;
        float ln = (y[k] - mn) * inv;
        g_luma[b * NN + p] = ln;
        sPad[(p / 48 + 1) * 50 + (p % 48) + 1] = 1.f - ln;
    }
    __syncthreads();

    float pooled[9];
    float ls = 0.f;
#pragma unroll
    for (int k = 0; k < 9; k++) {
        int p = t + k * 256;
        int base = (p / 48) * 50 + (p % 48);
        float s0 = 0.f;
#pragma unroll
        for (int a = 0; a < 3; a++)
#pragma unroll
            for (int c2 = 0; c2 < 3; c2++) s0 += sPad[base + a * 50 + c2];
        s0 *= (1.f / 9.f);
        pooled[k] = s0;
        ls += s0;
    }
    red[t] = ls; __syncthreads();
    for (int s = 128; s > 0; s >>= 1) { if (t < s) red[t] += red[t + s]; __syncthreads(); }
    float mean = red[0] * (1.f / 2304.f);
    float alpha = *alphap;
#pragma unroll
    for (int k = 0; k < 9; k++) {
        int p = t + k * 256;
        g_bias[b * NN + p] = alpha * (pooled[k] - mean);
    }
}

// ---------------- K2: conv1 (1 -> 128, 3x3, relu) ----------------
__global__ void conv1_kernel(const float* __restrict__ w, const float* __restrict__ bias) {
    __shared__ float sPad[2500];
    int b = blockIdx.x / HID, oc = blockIdx.x % HID;
    int t = threadIdx.x;
    for (int i = t; i < 2500; i += 256) sPad[i] = 0.f;
    __syncthreads();
    const float* src = g_luma + b * NN;
    for (int i = t; i < NN; i += 256) sPad[(i / 48 + 1) * 50 + (i % 48) + 1] = src[i];
    __syncthreads();
    float wv[9];
#pragma unroll
    for (int k = 0; k < 9; k++) wv[k] = __ldg(&w[oc * 9 + k]);
    float bb = __ldg(&bias[oc]);
    int py = (t >> 4) * 3, px = (t & 15) * 3;
    float nb[5][5];
#pragma unroll
    for (int a = 0; a < 5; a++)
#pragma unroll
        for (int c2 = 0; c2 < 5; c2++) nb[a][c2] = sPad[(py + a) * 50 + px + c2];
    float* dst = g_h1 + (b * HID + oc) * NN;
#pragma unroll
    for (int i = 0; i < 3; i++)
#pragma unroll
        for (int j = 0; j < 3; j++) {
            float a0 = bb;
#pragma unroll
            for (int ky = 0; ky < 3; ky++)
#pragma unroll
                for (int kx = 0; kx < 3; kx++) a0 += wv[ky * 3 + kx] * nb[i + ky][j + kx];
            dst[(py + i) * 48 + px + j] = fmaxf(a0, 0.f);
        }
}

// ---------------- K3: conv2 (128 -> 128, 3x3, relu) + spatial mean ----------------
__global__ void conv2_kernel(const float* __restrict__ w, const float* __restrict__ bias) {
    __shared__ float sPad[2500];
    __shared__ float red[256];
    int b = blockIdx.x / HID, oc = blockIdx.x % HID;
    int t = threadIdx.x;
    for (int i = t; i < 2500; i += 256) sPad[i] = 0.f;
    int sidx[9];
#pragma unroll
    for (int k = 0; k < 9; k++) { int p = t + k * 256; sidx[k] = (p / 48 + 1) * 50 + (p % 48) + 1; }
    int py = (t >> 4) * 3, px = (t & 15) * 3;
    float bb = __ldg(&bias[oc]);
    float acc[9];
#pragma unroll
    for (int k = 0; k < 9; k++) acc[k] = bb;
    const float* wbase = w + oc * HID * 9;
    for (int ic = 0; ic < HID; ic++) {
        __syncthreads();
        const float* src = g_h1 + (b * HID + ic) * NN;
#pragma unroll
        for (int k = 0; k < 9; k++) sPad[sidx[k]] = src[t + k * 256];
        __syncthreads();
        float wv[9];
#pragma unroll
        for (int k = 0; k < 9; k++) wv[k] = __ldg(&wbase[ic * 9 + k]);
        float nb[5][5];
#pragma unroll
        for (int a = 0; a < 5; a++)
#pragma unroll
            for (int c2 = 0; c2 < 5; c2++) nb[a][c2] = sPad[(py + a) * 50 + px + c2];
#pragma unroll
        for (int i = 0; i < 3; i++)
#pragma unroll
            for (int j = 0; j < 3; j++)
#pragma unroll
                for (int ky = 0; ky < 3; ky++)
#pragma unroll
                    for (int kx = 0; kx < 3; kx++)
                        acc[i * 3 + j] += wv[ky * 3 + kx] * nb[i + ky][j + kx];
    }
    float ls = 0.f;
#pragma unroll
    for (int k = 0; k < 9; k++) ls += fmaxf(acc[k], 0.f);
    red[t] = ls; __syncthreads();
    for (int s = 128; s > 0; s >>= 1) { if (t < s) red[t] += red[t + s]; __syncthreads(); }
    if (t == 0) g_hm[b * HID + oc] = red[0] * (1.f / 2304.f);
}

// ---------------- K4: FiLM parameters (6 x GEMV 128->256) ----------------
__global__ void film_kernel(
    const float* __restrict__ gq_w, const float* __restrict__ gq_b,
    const float* __restrict__ bq_w, const float* __restrict__ bq_b,
    const float* __restrict__ gk_w, const float* __restrict__ gk_b,
    const float* __restrict__ bk_w, const float* __restrict__ bk_b,
    const float* __restrict__ gv_w, const float* __restrict__ gv_b,
    const float* __restrict__ bv_w, const float* __restrict__ bv_b) {
    __shared__ float sh[HID];
    int b = blockIdx.x, t = threadIdx.x;
    if (t < HID) sh[t] = g_hm[b * HID + t];
    __syncthreads();
    int o = t;
    float a0 = 0, a1 = 0, a2 = 0, a3 = 0, a4 = 0, a5 = 0;
    for (int h2 = 0; h2 < HID; h2++) {
        float hv = sh[h2];
        a0 += hv * gq_w[o * HID + h2];
        a1 += hv * bq_w[o * HID + h2];
        a2 += hv * gk_w[o * HID + h2];
        a3 += hv * bk_w[o * HID + h2];
        a4 += hv * gv_w[o * HID + h2];
        a5 += hv * bv_w[o * HID + h2];
    }
    g_gq[b * INNER + o] = a0 + gq_b[o];
    g_fbq[b * INNER + o] = a1 + bq_b[o];
    g_gk[b * INNER + o] = a2 + gk_b[o];
    g_fbk[b * INNER + o] = a3 + bk_b[o];
    g_gv[b * INNER + o] = a4 + gv_b[o];
    g_fbv[b * INNER + o] = a5 + bv_b[o];
}

// ---------------- K5: QKV projection GEMM + FiLM epilogue ----------------
__global__ void __launch_bounds__(256) qkv_kernel(
    const float* __restrict__ x,
    const float* __restrict__ wq, const float* __restrict__ bq,
    const float* __restrict__ wk, const float* __restrict__ bk,
    const float* __restrict__ wv, const float* __restrict__ bv) {
    __shared__ float sW[32 * 128];
    __shared__ float sX[32 * 128];
    int which = blockIdx.z % 3;
    int b = blockIdx.z / 3;
    const float* W; const float* wb; const float* gvec; const float* bvec; float* out;
    if (which == 0) { W = wq; wb = bq; gvec = g_gq + b * INNER; bvec = g_fbq + b * INNER; out = g_q + b * INNER * NN; }
    else if (which == 1) { W = wk; wb = bk; gvec = g_gk + b * INNER; bvec = g_fbk + b * INNER; out = g_k + b * INNER * NN; }
    else { W = wv; wb = bv; gvec = g_gv + b * INNER; bvec = g_fbv + b * INNER; out = g_v + b * INNER * NN; }

    int o0 = blockIdx.y * 128, n0 = blockIdx.x * 128;
    int t = threadIdx.x;
    int r = t >> 4, cc = t & 15;
    float acc[8][8];
#pragma unroll
    for (int i = 0; i < 8; i++)
#pragma unroll
        for (int j = 0; j < 8; j++) acc[i][j] = 0.f;

    const float* xb = x + b * CCH * NN;
    for (int c0 = 0; c0 < CCH; c0 += 32) {
        __syncthreads();
        {   // W tile, transposed into smem: sW[ck][o]
            int orow = t >> 1;
            int ckb = (t & 1) * 16;
            const float4* s4 = (const float4*)(W + (o0 + orow) * CCH + c0 + ckb);
            float4 v0 = s4[0], v1 = s4[1], v2 = s4[2], v3 = s4[3];
            float tmp[16] = {v0.x, v0.y, v0.z, v0.w, v1.x, v1.y, v1.z, v1.w,
                             v2.x, v2.y, v2.z, v2.w, v3.x, v3.y, v3.z, v3.w};
#pragma unroll
            for (int s = 0; s < 16; s++) sW[(ckb + s) * 128 + orow] = tmp[s];
        }
        {   // X tile: sX[ck][n]
            int row = t >> 3, cb = (t & 7) * 16;
            const float4* s4 = (const float4*)(xb + (c0 + row) * NN + n0 + cb);
            float4* d4 = (float4*)(sX + row * 128 + cb);
            d4[0] = s4[0]; d4[1] = s4[1]; d4[2] = s4[2]; d4[3] = s4[3];
        }
        __syncthreads();
        const float4* sW4 = (const float4*)sW;
        const float4* sX4 = (const float4*)sX;
#pragma unroll 8
        for (int ck = 0; ck < 32; ck++) {
            float4 wA = sW4[ck * 32 + r * 2], wB = sW4[ck * 32 + r * 2 + 1];
            float4 xA = sX4[ck * 32 + cc], xB = sX4[ck * 32 + 16 + cc];
            float wv2[8] = {wA.x, wA.y, wA.z, wA.w, wB.x, wB.y, wB.z, wB.w};
            float xv[8] = {xA.x, xA.y, xA.z, xA.w, xB.x, xB.y, xB.z, xB.w};
#pragma unroll
            for (int i = 0; i < 8; i++)
#pragma unroll
                for (int j = 0; j < 8; j++) acc[i][j] += wv2[i] * xv[j];
        }
    }
#pragma unroll
    for (int i = 0; i < 8; i++) {
        int o = o0 + r * 8 + i;
        float gg = gvec[o], bb2 = bvec[o], wbb = wb[o];
        float4 vA = make_float4(gg * (acc[i][0] + wbb) + bb2, gg * (acc[i][1] + wbb) + bb2,
                                gg * (acc[i][2] + wbb) + bb2, gg * (acc[i][3] + wbb) + bb2);
        float4 vB = make_float4(gg * (acc[i][4] + wbb) + bb2, gg * (acc[i][5] + wbb) + bb2,
                                gg * (acc[i][6] + wbb) + bb2, gg * (acc[i][7] + wbb) + bb2);
        *(float4*)(out + o * NN + n0 + cc * 4) = vA;
        *(float4*)(out + o * NN + n0 + 64 + cc * 4) = vB;
    }
}

// ---------------- K6: flash attention (fp32), 128x128 tiles ----------------
extern __shared__ float smem_attn[];
__global__ void __launch_bounds__(256) attn_kernel() {
    float* sQ = smem_attn;            // 32*128
    float* sK = smem_attn + 4096;     // 32*128
    float* sV = smem_attn + 8192;     // 32*132 (padded)
    float* sP = smem_attn + 12416;    // 128*128

    int bh = blockIdx.y;
    int b = bh >> 3, h = bh & 7;
    int base = (b * INNER + h * DHD) * NN;
    int qt0 = blockIdx.x * 128;
    int t = threadIdx.x, r = t >> 4, cc = t & 15;
    int row = t >> 3, cb = (t & 7) * 16;

    {   // load Q tile [32 d][128 q]
        const float4* s4 = (const float4*)(g_q + base + row * NN + qt0 + cb);
        float4* d4 = (float4*)(sQ + row * 128 + cb);
        d4[0] = s4[0]; d4[1] = s4[1]; d4[2] = s4[2]; d4[3] = s4[3];
    }

    float mrow[8], lrow[8], acc[8][2];
#pragma unroll
    for (int i = 0; i < 8; i++) { mrow[i] = -1e30f; lrow[i] = 0.f; acc[i][0] = 0.f; acc[i][1] = 0.f; }

    const float* biasb = g_bias + b * NN;
    const float4* sQ4 = (const float4*)sQ;
    const float4* sK4 = (const float4*)sK;
    const float4* sV4 = (const float4*)sV;
    const float4* sP4c = (const float4*)sP;
    float4* sP4 = (float4*)sP;

    for (int kt = 0; kt < 18; kt++) {
        int m0 = kt * 128;
        __syncthreads();
        {   // load K tile
            const float4* s4 = (const float4*)(g_k + base + row * NN + m0 + cb);
            float4* d4 = (float4*)(sK + row * 128 + cb);
            d4[0] = s4[0]; d4[1] = s4[1]; d4[2] = s4[2]; d4[3] = s4[3];
        }
        {   // load V tile (stride 132)
            const float4* s4 = (const float4*)(g_v + base + row * NN + m0 + cb);
            float4* d4 = (float4*)(sV + row * 132 + cb);
            d4[0] = s4[0]; d4[1] = s4[1]; d4[2] = s4[2]; d4[3] = s4[3];
        }
        __syncthreads();

        // ---- S = Q^T K ----
        float s[8][8];
#pragma unroll
        for (int i = 0; i < 8; i++)
#pragma unroll
            for (int j = 0; j < 8; j++) s[i][j] = 0.f;
#pragma unroll 8
        for (int d = 0; d < 32; d++) {
            float4 qA = sQ4[d * 32 + r * 2], qB = sQ4[d * 32 + r * 2 + 1];
            float4 kA = sK4[d * 32 + cc], kB = sK4[d * 32 + 16 + cc];
            float qv[8] = {qA.x, qA.y, qA.z, qA.w, qB.x, qB.y, qB.z, qB.w};
            float kv[8] = {kA.x, kA.y, kA.z, kA.w, kB.x, kB.y, kB.z, kB.w};
#pragma unroll
            for (int i = 0; i < 8; i++)
#pragma unroll
                for (int j = 0; j < 8; j++) s[i][j] += qv[i] * kv[j];
        }
        // scale + key bias
        float4 bA = *(const float4*)(biasb + m0 + cc * 4);
        float4 bB = *(const float4*)(biasb + m0 + 64 + cc * 4);
        float bj[8] = {bA.x, bA.y, bA.z, bA.w, bB.x, bB.y, bB.z, bB.w};
#pragma unroll
        for (int i = 0; i < 8; i++)
#pragma unroll
            for (int j = 0; j < 8; j++) s[i][j] = s[i][j] * ATT_SCALE + bj[j];

        // ---- online softmax ----
#pragma unroll
        for (int i = 0; i < 8; i++) {
            float tm = s[i][0];
#pragma unroll
            for (int j = 1; j < 8; j++) tm = fmaxf(tm, s[i][j]);
#pragma unroll
            for (int off = 8; off > 0; off >>= 1) tm = fmaxf(tm, __shfl_xor_sync(0xffffffffu, tm, off, 16));
            float newm = fmaxf(mrow[i], tm);
            float scalef = __expf(mrow[i] - newm);
            mrow[i] = newm;
            float ts = 0.f;
#pragma unroll
            for (int j = 0; j < 8; j++) { s[i][j] = __expf(s[i][j] - newm); ts += s[i][j]; }
#pragma unroll
            for (int off = 8; off > 0; off >>= 1) ts += __shfl_xor_sync(0xffffffffu, ts, off, 16);
            lrow[i] = lrow[i] * scalef + ts;
            acc[i][0] *= scalef;
            acc[i][1] *= scalef;
            int q = r * 8 + i;
            sP4[q * 32 + cc] = make_float4(s[i][0], s[i][1], s[i][2], s[i][3]);
            sP4[q * 32 + 16 + cc] = make_float4(s[i][4], s[i][5], s[i][6], s[i][7]);
        }
        __syncthreads();

        // ---- O += P V^T ----
#pragma unroll 4
        for (int mb = 0; mb < 32; mb++) {
            float4 v0 = sV4[cc * 33 + mb];
            float4 v1 = sV4[(cc + 16) * 33 + mb];
#pragma unroll
            for (int i = 0; i < 8; i++) {
                float4 p4 = sP4c[(r * 8 + i) * 32 + mb];
                acc[i][0] += p4.x * v0.x + p4.y * v0.y + p4.z * v0.z + p4.w * v0.w;
                acc[i][1] += p4.x * v1.x + p4.y * v1.y + p4.z * v1.z + p4.w * v1.w;
            }
        }
    }

    // ---- finalize, stage through smem, coalesced store ----
    __syncthreads();
#pragma unroll
    for (int i = 0; i < 8; i++) {
        int q = r * 8 + i;
        float il = 1.f / lrow[i];
        sP[cc * 132 + q] = acc[i][0] * il;
        sP[(cc + 16) * 132 + q] = acc[i][1] * il;
    }
    __syncthreads();
    {
        const float4* s4 = (const float4*)(sP + row * 132 + cb);
        float4* d4 = (float4*)(g_O + base + row * NN + qt0 + cb);
        d4[0] = s4[0]; d4[1] = s4[1]; d4[2] = s4[2]; d4[3] = s4[3];
    }
}

// ---------------- K7: output projection GEMM ----------------
__global__ void __launch_bounds__(256) proj_kernel(
    const float* __restrict__ W, const float* __restrict__ wb, float* __restrict__ out0) {
    __shared__ float sW[32 * 128];
    __shared__ float sX[32 * 128];
    int b = blockIdx.z;
    const float* X = g_O + b * INNER * NN;
    float* out = out0 + b * CCH * NN;
    int o0 = blockIdx.y * 128, n0 = blockIdx.x * 128;
    int t = threadIdx.x;
    int r = t >> 4, cc = t & 15;
    float acc[8][8];
#pragma unroll
    for (int i = 0; i < 8; i++)
#pragma unroll
        for (int j = 0; j < 8; j++) acc[i][j] = 0.f;

    for (int c0 = 0; c0 < INNER; c0 += 32) {
        __syncthreads();
        {
            int orow = t >> 1;
            int ckb = (t & 1) * 16;
            const float4* s4 = (const float4*)(W + (o0 + orow) * INNER + c0 + ckb);
            float4 v0 = s4[0], v1 = s4[1], v2 = s4[2], v3 = s4[3];
            float tmp[16] = {v0.x, v0.y, v0.z, v0.w, v1.x, v1.y, v1.z, v1.w,
                             v2.x, v2.y, v2.z, v2.w, v3.x, v3.y, v3.z, v3.w};
#pragma unroll
            for (int s = 0; s < 16; s++) sW[(ckb + s) * 128 + orow] = tmp[s];
        }
        {
            int row = t >> 3, cb = (t & 7) * 16;
            const float4* s4 = (const float4*)(X + (c0 + row) * NN + n0 + cb);
            float4* d4 = (float4*)(sX + row * 128 + cb);
            d4[0] = s4[0]; d4[1] = s4[1]; d4[2] = s4[2]; d4[3] = s4[3];
        }
        __syncthreads();
        const float4* sW4 = (const float4*)sW;
        const float4* sX4 = (const float4*)sX;
#pragma unroll 8
        for (int ck = 0; ck < 32; ck++) {
            float4 wA = sW4[ck * 32 + r * 2], wB = sW4[ck * 32 + r * 2 + 1];
            float4 xA = sX4[ck * 32 + cc], xB = sX4[ck * 32 + 16 + cc];
            float wv2[8] = {wA.x, wA.y, wA.z, wA.w, wB.x, wB.y, wB.z, wB.w};
            float xv[8] = {xA.x, xA.y, xA.z, xA.w, xB.x, xB.y, xB.z, xB.w};
#pragma unroll
            for (int i = 0; i < 8; i++)
#pragma unroll
                for (int j = 0; j < 8; j++) acc[i][j] += wv2[i] * xv[j];
        }
    }
#pragma unroll
    for (int i = 0; i < 8; i++) {
        int o = o0 + r * 8 + i;
        float bb2 = wb[o];
        float4 vA = make_float4(acc[i][0] + bb2, acc[i][1] + bb2, acc[i][2] + bb2, acc[i][3] + bb2);
        float4 vB = make_float4(acc[i][4] + bb2, acc[i][5] + bb2, acc[i][6] + bb2, acc[i][7] + bb2);
        *(float4*)(out + o * NN + n0 + cc * 4) = vA;
        *(float4*)(out + o * NN + n0 + 64 + cc * 4) = vB;
    }
}

// ---------------- launch ----------------
extern "C" void kernel_launch(void* const* d_in, const int* in_sizes, int n_in,
                              void* d_out, int out_size) {
    const float* x      = (const float*)d_in[0];
    const float* rgb    = (const float*)d_in[1];
    const float* wq     = (const float*)d_in[2];
    const float* bq     = (const float*)d_in[3];
    const float* wk     = (const float*)d_in[4];
    const float* bk     = (const float*)d_in[5];
    const float* wv     = (const float*)d_in[6];
    const float* bv     = (const float*)d_in[7];
    const float* wproj  = (const float*)d_in[8];
    const float* bproj  = (const float*)d_in[9];
    const float* c1_w   = (const float*)d_in[10];
    const float* c1_b   = (const float*)d_in[11];
    const float* c2_w   = (const float*)d_in[12];
    const float* c2_b   = (const float*)d_in[13];
    const float* gq_w   = (const float*)d_in[14];
    const float* gq_b   = (const float*)d_in[15];
    const float* bqf_w  = (const float*)d_in[16];
    const float* bqf_b  = (const float*)d_in[17];
    const float* gk_w   = (const float*)d_in[18];
    const float* gk_b   = (const float*)d_in[19];
    const float* bkf_w  = (const float*)d_in[20];
    const float* bkf_b  = (const float*)d_in[21];
    const float* gv_w   = (const float*)d_in[22];
    const float* gv_b   = (const float*)d_in[23];
    const float* bvf_w  = (const float*)d_in[24];
    const float* bvf_b  = (const float*)d_in[25];
    const float* alpha  = (const float*)d_in[26];

    luma_kernel<<<BB, 256>>>(rgb, alpha);
    conv1_kernel<<<BB * HID, 256>>>(c1_w, c1_b);
    conv2_kernel<<<BB * HID, 256>>>(c2_w, c2_b);
    film_kernel<<<BB, 256>>>(gq_w, gq_b, bqf_w, bqf_b, gk_w, gk_b, bkf_w, bkf_b,
                             gv_w, gv_b, bvf_w, bvf_b);
    qkv_kernel<<<dim3(18, 2, 12), 256>>>(x, wq, bq, wk, bk, wv, bv);

    const int ATTN_SMEM = (4096 + 4096 + 32 * 132 + 128 * 128) * 4;  // 115200 B
    cudaFuncSetAttribute(attn_kernel, cudaFuncAttributeMaxDynamicSharedMemorySize, ATTN_SMEM);
    attn_kernel<<<dim3(18, 32), 256, ATTN_SMEM>>>();

    proj_kernel<<<dim3(18, 2, 4), 256>>>(wproj, bproj, (float*)d_out);
}

// round 2
// speedup vs baseline: 1.1789x; 1.1789x over previous
#include <cuda_runtime.h>

#define BB 4
#define CCH 256
#define HH 48
#define NN 2304
#define NHEADS 8
#define DHD 32
#define INNER 256
#define HID 128
#define ATT_SCALE 0.17677669529663687f
#define EPSV 1e-6f

// ---------- packed f32x2 helpers (sm_103a FFMA2: 2 MACs / instruction) ----------
#define FMA2(acc, a, b)  asm("fma.rn.f32x2 %0, %1, %2, %0;" : "+l"(acc) : "l"(a), "l"(b))
#define FMA2G(d, a, b, c) asm("fma.rn.f32x2 %0, %1, %2, %3;" : "=l"(d) : "l"(a), "l"(b), "l"(c))
#define MUL2(d, a, b)    asm("mul.rn.f32x2 %0, %1, %2;" : "=l"(d) : "l"(a), "l"(b))
#define SPLAT2(d, f)     asm("mov.b64 %0, {%1, %1};" : "=l"(d) : "f"(f))
#define PACK2(d, lo, hi) asm("mov.b64 %0, {%1, %2};" : "=l"(d) : "f"(lo), "f"(hi))
#define UNPACK2(lo, hi, v) asm("mov.b64 {%0, %1}, %2;" : "=f"(lo), "=f"(hi) : "l"(v))
typedef unsigned long long u64;

// ---------------- scratch ----------------
__device__ float g_luma[BB * NN];
__device__ float g_bias[BB * NN];
__device__ float g_h1[BB * HID * NN];
__device__ float g_hm[BB * HID];
__device__ float g_film[6 * BB * INNER];   // gq,fbq,gk,fbk,gv,fbv
__device__ float g_q[BB * INNER * NN];
__device__ float g_k[BB * INNER * NN];
__device__ float g_v[BB * INNER * NN];
__device__ float g_O[BB * INNER * NN];

// ---------------- K1: luma + normalization + pooled bias ----------------
__global__ void luma_kernel(const float* __restrict__ rgb, const float* __restrict__ alphap) {
    __shared__ float sPad[50 * 50];
    __shared__ float red[256];
    int b = blockIdx.x;
    int t = threadIdx.x;
    for (int i = t; i < 2500; i += 256) sPad[i] = 0.f;

    const float* rp = rgb + b * 3 * NN;
    float y[9];
    float mn = 1e30f, mx = -1e30f;
#pragma unroll
    for (int k = 0; k < 9; k++) {
        int p = t + k * 256;
        float yy = 0.299f * rp[p] + 0.587f * rp[NN + p] + 0.114f * rp[2 * NN + p];
        y[k] = yy;
        mn = fminf(mn, yy);
        mx = fmaxf(mx, yy);
    }
    red[t] = mn; __syncthreads();
    for (int s = 128; s > 0; s >>= 1) { if (t < s) red[t] = fminf(red[t], red[t + s]); __syncthreads(); }
    mn = red[0]; __syncthreads();
    red[t] = mx; __syncthreads();
    for (int s = 128; s > 0; s >>= 1) { if (t < s) red[t] = fmaxf(red[t], red[t + s]); __syncthreads(); }
    mx = red[0]; __syncthreads();

    float inv = 1.f / (mx - mn + EPSV);
#pragma unroll
    for (int k = 0; k < 9; k++) {
        int p = t + k * 256;
        float ln = (y[k] - mn) * inv;
        g_luma[b * NN + p] = ln;
        sPad[(p / 48 + 1) * 50 + (p % 48) + 1] = 1.f - ln;
    }
    __syncthreads();

    float pooled[9];
    float ls = 0.f;
#pragma unroll
    for (int k = 0; k < 9; k++) {
        int p = t + k * 256;
        int base = (p / 48) * 50 + (p % 48);
        float s0 = 0.f;
#pragma unroll
        for (int a = 0; a < 3; a++)
#pragma unroll
            for (int c2 = 0; c2 < 3; c2++) s0 += sPad[base + a * 50 + c2];
        s0 *= (1.f / 9.f);
        pooled[k] = s0;
        ls += s0;
    }
    red[t] = ls; __syncthreads();
    for (int s = 128; s > 0; s >>= 1) { if (t < s) red[t] += red[t + s]; __syncthreads(); }
    float mean = red[0] * (1.f / 2304.f);
    float alpha = *alphap;
#pragma unroll
    for (int k = 0; k < 9; k++) {
        int p = t + k * 256;
        g_bias[b * NN + p] = alpha * (pooled[k] - mean);
    }
}

// ---------------- K2: conv1 (1 -> 128, 3x3, relu), 16 oc per block ----------------
__global__ void __launch_bounds__(256) conv1_kernel(const float* __restrict__ w, const float* __restrict__ bias) {
    __shared__ float sPad[2500];
    int b = blockIdx.y, ocg = blockIdx.x * 16;
    int t = threadIdx.x;
    for (int i = t; i < 2500; i += 256) sPad[i] = 0.f;
    __syncthreads();
    const float* src = g_luma + b * NN;
    for (int i = t; i < NN; i += 256) sPad[(i / 48 + 1) * 50 + (i % 48) + 1] = src[i];
    __syncthreads();
    int py = (t >> 4) * 3, px = (t & 15) * 3;
    float nb[5][5];
#pragma unroll
    for (int a = 0; a < 5; a++)
#pragma unroll
        for (int c2 = 0; c2 < 5; c2++) nb[a][c2] = sPad[(py + a) * 50 + px + c2];

    for (int o = 0; o < 16; o++) {
        int oc = ocg + o;
        float wv[9];
#pragma unroll
        for (int k = 0; k < 9; k++) wv[k] = __ldg(&w[oc * 9 + k]);
        float bb = __ldg(&bias[oc]);
        float* dst = g_h1 + (b * HID + oc) * NN;
#pragma unroll
        for (int i = 0; i < 3; i++)
#pragma unroll
            for (int j = 0; j < 3; j++) {
                float a0 = bb;
#pragma unroll
                for (int ky = 0; ky < 3; ky++)
#pragma unroll
                    for (int kx = 0; kx < 3; kx++) a0 += wv[ky * 3 + kx] * nb[i + ky][j + kx];
                dst[(py + i) * 48 + px + j] = fmaxf(a0, 0.f);
            }
    }
}

// ---------------- K3: conv2 (128 -> 128, 3x3, relu) + mean; 4 oc per block, packed ----------------
__global__ void __launch_bounds__(256) conv2_kernel(const float* __restrict__ w, const float* __restrict__ bias) {
    __shared__ float sPad[2500];
    __shared__ u64 sW2[1152 * 2];   // [ic*9+tap][pair] pair p -> oc (ocg+2p, ocg+2p+1)
    __shared__ float red[256];
    int b = blockIdx.y, ocg = blockIdx.x * 4;
    int t = threadIdx.x;
    for (int i = t; i < 2500; i += 256) sPad[i] = 0.f;
    // pack weights: 2304 u64
    for (int idx = t; idx < 2304; idx += 256) {
        int pair = idx & 1, wi = idx >> 1;
        int oc = ocg + pair * 2;
        float lo = __ldg(&w[oc * 1152 + wi]);
        float hi = __ldg(&w[(oc + 1) * 1152 + wi]);
        u64 pk; PACK2(pk, lo, hi);
        sW2[idx] = pk;
    }
    int sidx[9];
#pragma unroll
    for (int k = 0; k < 9; k++) { int p = t + k * 256; sidx[k] = (p / 48 + 1) * 50 + (p % 48) + 1; }
    int py = (t >> 4) * 3, px = (t & 15) * 3;

    u64 bias0, bias1;
    PACK2(bias0, __ldg(&bias[ocg]), __ldg(&bias[ocg + 1]));
    PACK2(bias1, __ldg(&bias[ocg + 2]), __ldg(&bias[ocg + 3]));
    u64 acc2[2][9];
#pragma unroll
    for (int k = 0; k < 9; k++) { acc2[0][k] = bias0; acc2[1][k] = bias1; }

    for (int ic = 0; ic < HID; ic++) {
        __syncthreads();
        const float* src = g_h1 + (b * HID + ic) * NN;
#pragma unroll
        for (int k = 0; k < 9; k++) sPad[sidx[k]] = src[t + k * 256];
        __syncthreads();
        float nb[5][5];
#pragma unroll
        for (int a = 0; a < 5; a++)
#pragma unroll
            for (int c2 = 0; c2 < 5; c2++) nb[a][c2] = sPad[(py + a) * 50 + px + c2];
        const u64* wrow = sW2 + ic * 18;
#pragma unroll
        for (int ky = 0; ky < 3; ky++)
#pragma unroll
            for (int kx = 0; kx < 3; kx++) {
                int tap = ky * 3 + kx;
                u64 w0 = wrow[tap * 2], w1 = wrow[tap * 2 + 1];
#pragma unroll
                for (int i = 0; i < 3; i++)
#pragma unroll
                    for (int j = 0; j < 3; j++) {
                        u64 nb2; SPLAT2(nb2, nb[i + ky][j + kx]);
                        FMA2(acc2[0][i * 3 + j], nb2, w0);
                        FMA2(acc2[1][i * 3 + j], nb2, w1);
                    }
            }
    }
    float ls[4] = {0.f, 0.f, 0.f, 0.f};
#pragma unroll
    for (int k = 0; k < 9; k++) {
        float v0, v1, v2, v3;
        UNPACK2(v0, v1, acc2[0][k]);
        UNPACK2(v2, v3, acc2[1][k]);
        ls[0] += fmaxf(v0, 0.f); ls[1] += fmaxf(v1, 0.f);
        ls[2] += fmaxf(v2, 0.f); ls[3] += fmaxf(v3, 0.f);
    }
#pragma unroll
    for (int o4 = 0; o4 < 4; o4++) {
        __syncthreads();
        red[t] = ls[o4]; __syncthreads();
        for (int s = 128; s > 0; s >>= 1) { if (t < s) red[t] += red[t + s]; __syncthreads(); }
        if (t == 0) g_hm[b * HID + ocg + o4] = red[0] * (1.f / 2304.f);
    }
}

// ---------------- K4: FiLM params (6 GEMV 128->256), warp-per-row ----------------
__global__ void __launch_bounds__(256) film_kernel(
    const float* __restrict__ gq_w, const float* __restrict__ gq_b,
    const float* __restrict__ bq_w, const float* __restrict__ bq_b,
    const float* __restrict__ gk_w, const float* __restrict__ gk_b,
    const float* __restrict__ bk_w, const float* __restrict__ bk_b,
    const float* __restrict__ gv_w, const float* __restrict__ gv_b,
    const float* __restrict__ bv_w, const float* __restrict__ bv_b) {
    __shared__ float sh[HID];
    int mat = blockIdx.x, b = blockIdx.y;
    const float* W; const float* bs;
    switch (mat) {
        case 0: W = gq_w; bs = gq_b; break;
        case 1: W = bq_w; bs = bq_b; break;
        case 2: W = gk_w; bs = gk_b; break;
        case 3: W = bk_w; bs = bk_b; break;
        case 4: W = gv_w; bs = gv_b; break;
        default: W = bv_w; bs = bv_b; break;
    }
    float* out = g_film + (mat * BB + b) * INNER;
    int t = threadIdx.x, wp = t >> 5, l = t & 31;
    if (t < HID) sh[t] = g_hm[b * HID + t];
    __syncthreads();
    float h0 = sh[l], h1 = sh[l + 32], h2 = sh[l + 64], h3 = sh[l + 96];
    for (int k = 0; k < 32; k++) {
        int o = wp * 32 + k;
        const float* wr = W + o * HID;
        float p = h0 * wr[l] + h1 * wr[l + 32] + h2 * wr[l + 64] + h3 * wr[l + 96];
#pragma unroll
        for (int off = 16; off > 0; off >>= 1) p += __shfl_xor_sync(0xffffffffu, p, off);
        if (l == 0) out[o] = p + __ldg(&bs[o]);
    }
}

// ---------------- K5: QKV projection GEMM + FiLM epilogue (FFMA2) ----------------
__global__ void __launch_bounds__(256) qkv_kernel(
    const float* __restrict__ x,
    const float* __restrict__ wq, const float* __restrict__ bq,
    const float* __restrict__ wk, const float* __restrict__ bk,
    const float* __restrict__ wv, const float* __restrict__ bv) {
    __shared__ float sW[32 * 128];
    __shared__ float sX[32 * 128];
    int which = blockIdx.z % 3;
    int b = blockIdx.z / 3;
    const float* W; const float* wb; const float* gvec; const float* bvec; float* out;
    if (which == 0) { W = wq; wb = bq; gvec = g_film + (0 * BB + b) * INNER; bvec = g_film + (1 * BB + b) * INNER; out = g_q + b * INNER * NN; }
    else if (which == 1) { W = wk; wb = bk; gvec = g_film + (2 * BB + b) * INNER; bvec = g_film + (3 * BB + b) * INNER; out = g_k + b * INNER * NN; }
    else { W = wv; wb = bv; gvec = g_film + (4 * BB + b) * INNER; bvec = g_film + (5 * BB + b) * INNER; out = g_v + b * INNER * NN; }

    int o0 = blockIdx.y * 128, n0 = blockIdx.x * 128;
    int t = threadIdx.x;
    int r = t >> 4, cc = t & 15;
    u64 acc2[8][4];
#pragma unroll
    for (int i = 0; i < 8; i++)
#pragma unroll
        for (int j = 0; j < 4; j++) acc2[i][j] = 0ull;

    const float* xb = x + b * CCH * NN;
    const float4* sW4 = (const float4*)sW;
    const ulonglong2* sX2 = (const ulonglong2*)sX;
    for (int c0 = 0; c0 < CCH; c0 += 32) {
        __syncthreads();
        {   // W tile transposed into smem: sW[ck][o]
            int orow = t >> 1;
            int ckb = (t & 1) * 16;
            const float4* s4 = (const float4*)(W + (o0 + orow) * CCH + c0 + ckb);
            float4 v0 = s4[0], v1 = s4[1], v2 = s4[2], v3 = s4[3];
            float tmp[16] = {v0.x, v0.y, v0.z, v0.w, v1.x, v1.y, v1.z, v1.w,
                             v2.x, v2.y, v2.z, v2.w, v3.x, v3.y, v3.z, v3.w};
#pragma unroll
            for (int s = 0; s < 16; s++) sW[(ckb + s) * 128 + orow] = tmp[s];
        }
        {   // X tile: sX[ck][n]
            int row = t >> 3, cb = (t & 7) * 16;
            const float4* s4 = (const float4*)(xb + (c0 + row) * NN + n0 + cb);
            float4* d4 = (float4*)(sX + row * 128 + cb);
            d4[0] = s4[0]; d4[1] = s4[1]; d4[2] = s4[2]; d4[3] = s4[3];
        }
        __syncthreads();
#pragma unroll 4
        for (int ck = 0; ck < 32; ck++) {
            float4 wA = sW4[ck * 32 + r * 2], wB = sW4[ck * 32 + r * 2 + 1];
            ulonglong2 xA = sX2[ck * 32 + cc], xB = sX2[ck * 32 + 16 + cc];
            float wvv[8] = {wA.x, wA.y, wA.z, wA.w, wB.x, wB.y, wB.z, wB.w};
#pragma unroll
            for (int i = 0; i < 8; i++) {
                u64 w2; SPLAT2(w2, wvv[i]);
                FMA2(acc2[i][0], w2, xA.x);
                FMA2(acc2[i][1], w2, xA.y);
                FMA2(acc2[i][2], w2, xB.x);
                FMA2(acc2[i][3], w2, xB.y);
            }
        }
    }
#pragma unroll
    for (int i = 0; i < 8; i++) {
        int o = o0 + r * 8 + i;
        float gg = gvec[o], bb2 = bvec[o], wbb = wb[o];
        float a[8];
        UNPACK2(a[0], a[1], acc2[i][0]);
        UNPACK2(a[2], a[3], acc2[i][1]);
        UNPACK2(a[4], a[5], acc2[i][2]);
        UNPACK2(a[6], a[7], acc2[i][3]);
        float4 vA = make_float4(gg * (a[0] + wbb) + bb2, gg * (a[1] + wbb) + bb2,
                                gg * (a[2] + wbb) + bb2, gg * (a[3] + wbb) + bb2);
        float4 vB = make_float4(gg * (a[4] + wbb) + bb2, gg * (a[5] + wbb) + bb2,
                                gg * (a[6] + wbb) + bb2, gg * (a[7] + wbb) + bb2);
        *(float4*)(out + o * NN + n0 + cc * 4) = vA;
        *(float4*)(out + o * NN + n0 + 64 + cc * 4) = vB;
    }
}

// ---------------- K6: flash attention (FFMA2), 128x128 tiles ----------------
extern __shared__ float smem_attn[];
__global__ void __launch_bounds__(256) attn_kernel() {
    float* sQ = smem_attn;            // 32*128
    float* sK = smem_attn + 4096;     // 32*128
    float* sV = smem_attn + 8192;     // 32*132 (padded)
    float* sP = smem_attn + 12416;    // 128*128

    int bh = blockIdx.y;
    int b = bh >> 3, h = bh & 7;
    int base = (b * INNER + h * DHD) * NN;
    int qt0 = blockIdx.x * 128;
    int t = threadIdx.x, r = t >> 4, cc = t & 15;
    int row = t >> 3, cb = (t & 7) * 16;

    {   // load Q tile [32 d][128 q]
        const float4* s4 = (const float4*)(g_q + base + row * NN + qt0 + cb);
        float4* d4 = (float4*)(sQ + row * 128 + cb);
        d4[0] = s4[0]; d4[1] = s4[1]; d4[2] = s4[2]; d4[3] = s4[3];
    }

    float mrow[8], lrow[8];
    u64 o2[8][2];
#pragma unroll
    for (int i = 0; i < 8; i++) { mrow[i] = -1e30f; lrow[i] = 0.f; o2[i][0] = 0ull; o2[i][1] = 0ull; }

    const float* biasb = g_bias + b * NN;
    const float4* sQ4 = (const float4*)sQ;
    const ulonglong2* sK2 = (const ulonglong2*)sK;
    const ulonglong2* sV2 = (const ulonglong2*)sV;
    const ulonglong2* sP2 = (const ulonglong2*)sP;
    float4* sP4 = (float4*)sP;

    u64 scale2; SPLAT2(scale2, ATT_SCALE);

    for (int kt = 0; kt < 18; kt++) {
        int m0 = kt * 128;
        __syncthreads();
        {   // load K tile
            const float4* s4 = (const float4*)(g_k + base + row * NN + m0 + cb);
            float4* d4 = (float4*)(sK + row * 128 + cb);
            d4[0] = s4[0]; d4[1] = s4[1]; d4[2] = s4[2]; d4[3] = s4[3];
        }
        {   // load V tile (stride 132)
            const float4* s4 = (const float4*)(g_v + base + row * NN + m0 + cb);
            float4* d4 = (float4*)(sV + row * 132 + cb);
            d4[0] = s4[0]; d4[1] = s4[1]; d4[2] = s4[2]; d4[3] = s4[3];
        }
        __syncthreads();

        // ---- S = Q^T K (packed along m) ----
        u64 s2[8][4];
#pragma unroll
        for (int i = 0; i < 8; i++)
#pragma unroll
            for (int j = 0; j < 4; j++) s2[i][j] = 0ull;
#pragma unroll 8
        for (int d = 0; d < 32; d++) {
            float4 qA = sQ4[d * 32 + r * 2], qB = sQ4[d * 32 + r * 2 + 1];
            ulonglong2 kA = sK2[d * 32 + cc], kB = sK2[d * 32 + 16 + cc];
            float qv[8] = {qA.x, qA.y, qA.z, qA.w, qB.x, qB.y, qB.z, qB.w};
#pragma unroll
            for (int i = 0; i < 8; i++) {
                u64 q2; SPLAT2(q2, qv[i]);
                FMA2(s2[i][0], q2, kA.x);
                FMA2(s2[i][1], q2, kA.y);
                FMA2(s2[i][2], q2, kB.x);
                FMA2(s2[i][3], q2, kB.y);
            }
        }
        // scale + key bias (packed)
        ulonglong2 bA = *(const ulonglong2*)(biasb + m0 + cc * 4);
        ulonglong2 bB = *(const ulonglong2*)(biasb + m0 + 64 + cc * 4);
        float s[8][8];
#pragma unroll
        for (int i = 0; i < 8; i++) {
            u64 r0, r1, r2, r3;
            FMA2G(r0, s2[i][0], scale2, bA.x);
            FMA2G(r1, s2[i][1], scale2, bA.y);
            FMA2G(r2, s2[i][2], scale2, bB.x);
            FMA2G(r3, s2[i][3], scale2, bB.y);
            UNPACK2(s[i][0], s[i][1], r0);
            UNPACK2(s[i][2], s[i][3], r1);
            UNPACK2(s[i][4], s[i][5], r2);
            UNPACK2(s[i][6], s[i][7], r3);
        }

        // ---- online softmax ----
#pragma unroll
        for (int i = 0; i < 8; i++) {
            float tm = s[i][0];
#pragma unroll
            for (int j = 1; j < 8; j++) tm = fmaxf(tm, s[i][j]);
#pragma unroll
            for (int off = 8; off > 0; off >>= 1) tm = fmaxf(tm, __shfl_xor_sync(0xffffffffu, tm, off, 16));
            float newm = fmaxf(mrow[i], tm);
            float scalef = __expf(mrow[i] - newm);
            mrow[i] = newm;
            float ts = 0.f;
#pragma unroll
            for (int j = 0; j < 8; j++) { s[i][j] = __expf(s[i][j] - newm); ts += s[i][j]; }
#pragma unroll
            for (int off = 8; off > 0; off >>= 1) ts += __shfl_xor_sync(0xffffffffu, ts, off, 16);
            lrow[i] = lrow[i] * scalef + ts;
            u64 sc2; SPLAT2(sc2, scalef);
            MUL2(o2[i][0], o2[i][0], sc2);
            MUL2(o2[i][1], o2[i][1], sc2);
            int q = r * 8 + i;
            sP4[q * 32 + cc] = make_float4(s[i][0], s[i][1], s[i][2], s[i][3]);
            sP4[q * 32 + 16 + cc] = make_float4(s[i][4], s[i][5], s[i][6], s[i][7]);
        }
        __syncthreads();

        // ---- O += P V^T (packed along m-reduction; halves = m-parity partials) ----
#pragma unroll 4
        for (int mb = 0; mb < 32; mb++) {
            ulonglong2 v0 = sV2[cc * 33 + mb];
            ulonglong2 v1 = sV2[(cc + 16) * 33 + mb];
#pragma unroll
            for (int i = 0; i < 8; i++) {
                ulonglong2 p2 = sP2[(r * 8 + i) * 32 + mb];
                FMA2(o2[i][0], p2.x, v0.x);
                FMA2(o2[i][0], p2.y, v0.y);
                FMA2(o2[i][1], p2.x, v1.x);
                FMA2(o2[i][1], p2.y, v1.y);
            }
        }
    }

    // ---- finalize, stage through smem, coalesced store ----
    __syncthreads();
#pragma unroll
    for (int i = 0; i < 8; i++) {
        int q = r * 8 + i;
        float il = 1.f / lrow[i];
        float a0, a1, b0, b1;
        UNPACK2(a0, a1, o2[i][0]);
        UNPACK2(b0, b1, o2[i][1]);
        sP[cc * 132 + q] = (a0 + a1) * il;
        sP[(cc + 16) * 132 + q] = (b0 + b1) * il;
    }
    __syncthreads();
    {
        const float4* s4 = (const float4*)(sP + row * 132 + cb);
        float4* d4 = (float4*)(g_O + base + row * NN + qt0 + cb);
        d4[0] = s4[0]; d4[1] = s4[1]; d4[2] = s4[2]; d4[3] = s4[3];
    }
}

// ---------------- K7: output projection GEMM (FFMA2) ----------------
__global__ void __launch_bounds__(256) proj_kernel(
    const float* __restrict__ W, const float* __restrict__ wb, float* __restrict__ out0) {
    __shared__ float sW[32 * 128];
    __shared__ float sX[32 * 128];
    int b = blockIdx.z;
    const float* X = g_O + b * INNER * NN;
    float* out = out0 + b * CCH * NN;
    int o0 = blockIdx.y * 128, n0 = blockIdx.x * 128;
    int t = threadIdx.x;
    int r = t >> 4, cc = t & 15;
    u64 acc2[8][4];
#pragma unroll
    for (int i = 0; i < 8; i++)
#pragma unroll
        for (int j = 0; j < 4; j++) acc2[i][j] = 0ull;

    const float4* sW4 = (const float4*)sW;
    const ulonglong2* sX2 = (const ulonglong2*)sX;
    for (int c0 = 0; c0 < INNER; c0 += 32) {
        __syncthreads();
        {
            int orow = t >> 1;
            int ckb = (t & 1) * 16;
            const float4* s4 = (const float4*)(W + (o0 + orow) * INNER + c0 + ckb);
            float4 v0 = s4[0], v1 = s4[1], v2 = s4[2], v3 = s4[3];
            float tmp[16] = {v0.x, v0.y, v0.z, v0.w, v1.x, v1.y, v1.z, v1.w,
                             v2.x, v2.y, v2.z, v2.w, v3.x, v3.y, v3.z, v3.w};
#pragma unroll
            for (int s = 0; s < 16; s++) sW[(ckb + s) * 128 + orow] = tmp[s];
        }
        {
            int row = t >> 3, cb = (t & 7) * 16;
            const float4* s4 = (const float4*)(X + (c0 + row) * NN + n0 + cb);
            float4* d4 = (float4*)(sX + row * 128 + cb);
            d4[0] = s4[0]; d4[1] = s4[1]; d4[2] = s4[2]; d4[3] = s4[3];
        }
        __syncthreads();
#pragma unroll 4
        for (int ck = 0; ck < 32; ck++) {
            float4 wA = sW4[ck * 32 + r * 2], wB = sW4[ck * 32 + r * 2 + 1];
            ulonglong2 xA = sX2[ck * 32 + cc], xB = sX2[ck * 32 + 16 + cc];
            float wvv[8] = {wA.x, wA.y, wA.z, wA.w, wB.x, wB.y, wB.z, wB.w};
#pragma unroll
            for (int i = 0; i < 8; i++) {
                u64 w2; SPLAT2(w2, wvv[i]);
                FMA2(acc2[i][0], w2, xA.x);
                FMA2(acc2[i][1], w2, xA.y);
                FMA2(acc2[i][2], w2, xB.x);
                FMA2(acc2[i][3], w2, xB.y);
            }
        }
    }
#pragma unroll
    for (int i = 0; i < 8; i++) {
        int o = o0 + r * 8 + i;
        float bb2 = wb[o];
        float a[8];
        UNPACK2(a[0], a[1], acc2[i][0]);
        UNPACK2(a[2], a[3], acc2[i][1]);
        UNPACK2(a[4], a[5], acc2[i][2]);
        UNPACK2(a[6], a[7], acc2[i][3]);
        float4 vA = make_float4(a[0] + bb2, a[1] + bb2, a[2] + bb2, a[3] + bb2);
        float4 vB = make_float4(a[4] + bb2, a[5] + bb2, a[6] + bb2, a[7] + bb2);
        *(float4*)(out + o * NN + n0 + cc * 4) = vA;
        *(float4*)(out + o * NN + n0 + 64 + cc * 4) = vB;
    }
}

// ---------------- launch ----------------
extern "C" void kernel_launch(void* const* d_in, const int* in_sizes, int n_in,
                              void* d_out, int out_size) {
    const float* x      = (const float*)d_in[0];
    const float* rgb    = (const float*)d_in[1];
    const float* wq     = (const float*)d_in[2];
    const float* bq     = (const float*)d_in[3];
    const float* wk     = (const float*)d_in[4];
    const float* bk     = (const float*)d_in[5];
    const float* wv     = (const float*)d_in[6];
    const float* bv     = (const float*)d_in[7];
    const float* wproj  = (const float*)d_in[8];
    const float* bproj  = (const float*)d_in[9];
    const float* c1_w   = (const float*)d_in[10];
    const float* c1_b   = (const float*)d_in[11];
    const float* c2_w   = (const float*)d_in[12];
    const float* c2_b   = (const float*)d_in[13];
    const float* gq_w   = (const float*)d_in[14];
    const float* gq_b   = (const float*)d_in[15];
    const float* bqf_w  = (const float*)d_in[16];
    const float* bqf_b  = (const float*)d_in[17];
    const float* gk_w   = (const float*)d_in[18];
    const float* gk_b   = (const float*)d_in[19];
    const float* bkf_w  = (const float*)d_in[20];
    const float* bkf_b  = (const float*)d_in[21];
    const float* gv_w   = (const float*)d_in[22];
    const float* gv_b   = (const float*)d_in[23];
    const float* bvf_w  = (const float*)d_in[24];
    const float* bvf_b  = (const float*)d_in[25];
    const float* alpha  = (const float*)d_in[26];

    luma_kernel<<<BB, 256>>>(rgb, alpha);
    conv1_kernel<<<dim3(8, BB), 256>>>(c1_w, c1_b);
    conv2_kernel<<<dim3(32, BB), 256>>>(c2_w, c2_b);
    film_kernel<<<dim3(6, BB), 256>>>(gq_w, gq_b, bqf_w, bqf_b, gk_w, gk_b, bkf_w, bkf_b,
                                      gv_w, gv_b, bvf_w, bvf_b);
    qkv_kernel<<<dim3(18, 2, 12), 256>>>(x, wq, bq, wk, bk, wv, bv);

    const int ATTN_SMEM = (4096 + 4096 + 32 * 132 + 128 * 128) * 4;  // 115200 B
    cudaFuncSetAttribute(attn_kernel, cudaFuncAttributeMaxDynamicSharedMemorySize, ATTN_SMEM);
    attn_kernel<<<dim3(18, 32), 256, ATTN_SMEM>>>();

    proj_kernel<<<dim3(18, 2, 4), 256>>>(wproj, bproj, (float*)d_out);
}

// round 3
// speedup vs baseline: 1.8565x; 1.5748x over previous
#include <cuda_runtime.h>

#define BB 4
#define CCH 256
#define HH 48
#define NN 2304
#define NHEADS 8
#define DHD 32
#define INNER 256
#define HID 128
#define ATT_SCALE 0.17677669529663687f
#define EPSV 1e-6f

// ---------- packed f32x2 helpers ----------
#define FMA2(acc, a, b)  asm("fma.rn.f32x2 %0, %1, %2, %0;" : "+l"(acc) : "l"(a), "l"(b))
#define SPLAT2(d, f)     asm("mov.b64 %0, {%1, %1};" : "=l"(d) : "f"(f))
#define PACK2(d, lo, hi) asm("mov.b64 %0, {%1, %2};" : "=l"(d) : "f"(lo), "f"(hi))
#define UNPACK2(lo, hi, v) asm("mov.b64 {%0, %1}, %2;" : "=f"(lo), "=f"(hi) : "l"(v))
typedef unsigned long long u64;

// ---------- tf32 helpers ----------
#define CVT_TF32(d, f) asm("cvt.rna.tf32.f32 %0, %1;" : "=r"(d) : "f"(f))
#define MMA_TF32(c0,c1,c2,c3,a0,a1,a2,a3,b0,b1) \
  asm volatile("mma.sync.aligned.m16n8k8.row.col.f32.tf32.tf32.f32 " \
      "{%0,%1,%2,%3}, {%4,%5,%6,%7}, {%8,%9}, {%0,%1,%2,%3};" \
      : "+f"(c0), "+f"(c1), "+f"(c2), "+f"(c3) \
      : "r"(a0), "r"(a1), "r"(a2), "r"(a3), "r"(b0), "r"(b1))

// ---------------- scratch ----------------
__device__ float g_luma[BB * NN];
__device__ float g_bias[BB * NN];
__device__ float g_h1[BB * HID * NN];
__device__ float g_hm[BB * HID];
__device__ float g_film[6 * BB * INNER];
__device__ float g_q[BB * NHEADS * NN * DHD];   // token-major [B,H,N,32], tf32-rounded
__device__ float g_k[BB * NHEADS * NN * DHD];
__device__ float g_v[BB * NHEADS * NN * DHD];
__device__ float g_O[BB * INNER * NN];          // [o][n]

// ---------------- K1: luma + normalization + pooled bias ----------------
__global__ void luma_kernel(const float* __restrict__ rgb, const float* __restrict__ alphap) {
    __shared__ float sPad[50 * 50];
    __shared__ float red[256];
    int b = blockIdx.x;
    int t = threadIdx.x;
    for (int i = t; i < 2500; i += 256) sPad[i] = 0.f;

    const float* rp = rgb + b * 3 * NN;
    float y[9];
    float mn = 1e30f, mx = -1e30f;
#pragma unroll
    for (int k = 0; k < 9; k++) {
        int p = t + k * 256;
        float yy = 0.299f * rp[p] + 0.587f * rp[NN + p] + 0.114f * rp[2 * NN + p];
        y[k] = yy;
        mn = fminf(mn, yy);
        mx = fmaxf(mx, yy);
    }
    red[t] = mn; __syncthreads();
    for (int s = 128; s > 0; s >>= 1) { if (t < s) red[t] = fminf(red[t], red[t + s]); __syncthreads(); }
    mn = red[0]; __syncthreads();
    red[t] = mx; __syncthreads();
    for (int s = 128; s > 0; s >>= 1) { if (t < s) red[t] = fmaxf(red[t], red[t + s]); __syncthreads(); }
    mx = red[0]; __syncthreads();

    float inv = 1.f / (mx - mn + EPSV);
#pragma unroll
    for (int k = 0; k < 9; k++) {
        int p = t + k * 256;
        float ln = (y[k] - mn) * inv;
        g_luma[b * NN + p] = ln;
        sPad[(p / 48 + 1) * 50 + (p % 48) + 1] = 1.f - ln;
    }
    __syncthreads();

    float pooled[9];
    float ls = 0.f;
#pragma unroll
    for (int k = 0; k < 9; k++) {
        int p = t + k * 256;
        int base = (p / 48) * 50 + (p % 48);
        float s0 = 0.f;
#pragma unroll
        for (int a = 0; a < 3; a++)
#pragma unroll
            for (int c2 = 0; c2 < 3; c2++) s0 += sPad[base + a * 50 + c2];
        s0 *= (1.f / 9.f);
        pooled[k] = s0;
        ls += s0;
    }
    red[t] = ls; __syncthreads();
    for (int s = 128; s > 0; s >>= 1) { if (t < s) red[t] += red[t + s]; __syncthreads(); }
    float mean = red[0] * (1.f / 2304.f);
    float alpha = *alphap;
#pragma unroll
    for (int k = 0; k < 9; k++) {
        int p = t + k * 256;
        g_bias[b * NN + p] = alpha * (pooled[k] - mean);
    }
}

// ---------------- K2: conv1 ----------------
__global__ void __launch_bounds__(256) conv1_kernel(const float* __restrict__ w, const float* __restrict__ bias) {
    __shared__ float sPad[2500];
    int b = blockIdx.y, ocg = blockIdx.x * 16;
    int t = threadIdx.x;
    for (int i = t; i < 2500; i += 256) sPad[i] = 0.f;
    __syncthreads();
    const float* src = g_luma + b * NN;
    for (int i = t; i < NN; i += 256) sPad[(i / 48 + 1) * 50 + (i % 48) + 1] = src[i];
    __syncthreads();
    int py = (t >> 4) * 3, px = (t & 15) * 3;
    float nb[5][5];
#pragma unroll
    for (int a = 0; a < 5; a++)
#pragma unroll
        for (int c2 = 0; c2 < 5; c2++) nb[a][c2] = sPad[(py + a) * 50 + px + c2];

    for (int o = 0; o < 16; o++) {
        int oc = ocg + o;
        float wv[9];
#pragma unroll
        for (int k = 0; k < 9; k++) wv[k] = __ldg(&w[oc * 9 + k]);
        float bb = __ldg(&bias[oc]);
        float* dst = g_h1 + (b * HID + oc) * NN;
#pragma unroll
        for (int i = 0; i < 3; i++)
#pragma unroll
            for (int j = 0; j < 3; j++) {
                float a0 = bb;
#pragma unroll
                for (int ky = 0; ky < 3; ky++)
#pragma unroll
                    for (int kx = 0; kx < 3; kx++) a0 += wv[ky * 3 + kx] * nb[i + ky][j + kx];
                dst[(py + i) * 48 + px + j] = fmaxf(a0, 0.f);
            }
    }
}

// ---------------- K3: conv2 (FFMA2, 4 oc per block) ----------------
__global__ void __launch_bounds__(256) conv2_kernel(const float* __restrict__ w, const float* __restrict__ bias) {
    __shared__ float sPad[2500];
    __shared__ u64 sW2[1152 * 2];
    __shared__ float red[256];
    int b = blockIdx.y, ocg = blockIdx.x * 4;
    int t = threadIdx.x;
    for (int i = t; i < 2500; i += 256) sPad[i] = 0.f;
    for (int idx = t; idx < 2304; idx += 256) {
        int pair = idx & 1, wi = idx >> 1;
        int oc = ocg + pair * 2;
        float lo = __ldg(&w[oc * 1152 + wi]);
        float hi = __ldg(&w[(oc + 1) * 1152 + wi]);
        u64 pk; PACK2(pk, lo, hi);
        sW2[idx] = pk;
    }
    int sidx[9];
#pragma unroll
    for (int k = 0; k < 9; k++) { int p = t + k * 256; sidx[k] = (p / 48 + 1) * 50 + (p % 48) + 1; }
    int py = (t >> 4) * 3, px = (t & 15) * 3;

    u64 bias0, bias1;
    PACK2(bias0, __ldg(&bias[ocg]), __ldg(&bias[ocg + 1]));
    PACK2(bias1, __ldg(&bias[ocg + 2]), __ldg(&bias[ocg + 3]));
    u64 acc2[2][9];
#pragma unroll
    for (int k = 0; k < 9; k++) { acc2[0][k] = bias0; acc2[1][k] = bias1; }

    for (int ic = 0; ic < HID; ic++) {
        __syncthreads();
        const float* src = g_h1 + (b * HID + ic) * NN;
#pragma unroll
        for (int k = 0; k < 9; k++) sPad[sidx[k]] = src[t + k * 256];
        __syncthreads();
        float nb[5][5];
#pragma unroll
        for (int a = 0; a < 5; a++)
#pragma unroll
            for (int c2 = 0; c2 < 5; c2++) nb[a][c2] = sPad[(py + a) * 50 + px + c2];
        const u64* wrow = sW2 + ic * 18;
#pragma unroll
        for (int ky = 0; ky < 3; ky++)
#pragma unroll
            for (int kx = 0; kx < 3; kx++) {
                int tap = ky * 3 + kx;
                u64 w0 = wrow[tap * 2], w1 = wrow[tap * 2 + 1];
#pragma unroll
                for (int i = 0; i < 3; i++)
#pragma unroll
                    for (int j = 0; j < 3; j++) {
                        u64 nb2; SPLAT2(nb2, nb[i + ky][j + kx]);
                        FMA2(acc2[0][i * 3 + j], nb2, w0);
                        FMA2(acc2[1][i * 3 + j], nb2, w1);
                    }
            }
    }
    float ls[4] = {0.f, 0.f, 0.f, 0.f};
#pragma unroll
    for (int k = 0; k < 9; k++) {
        float v0, v1, v2, v3;
        UNPACK2(v0, v1, acc2[0][k]);
        UNPACK2(v2, v3, acc2[1][k]);
        ls[0] += fmaxf(v0, 0.f); ls[1] += fmaxf(v1, 0.f);
        ls[2] += fmaxf(v2, 0.f); ls[3] += fmaxf(v3, 0.f);
    }
#pragma unroll
    for (int o4 = 0; o4 < 4; o4++) {
        __syncthreads();
        red[t] = ls[o4]; __syncthreads();
        for (int s = 128; s > 0; s >>= 1) { if (t < s) red[t] += red[t + s]; __syncthreads(); }
        if (t == 0) g_hm[b * HID + ocg + o4] = red[0] * (1.f / 2304.f);
    }
}

// ---------------- K4: FiLM params ----------------
__global__ void __launch_bounds__(256) film_kernel(
    const float* __restrict__ gq_w, const float* __restrict__ gq_b,
    const float* __restrict__ bq_w, const float* __restrict__ bq_b,
    const float* __restrict__ gk_w, const float* __restrict__ gk_b,
    const float* __restrict__ bk_w, const float* __restrict__ bk_b,
    const float* __restrict__ gv_w, const float* __restrict__ gv_b,
    const float* __restrict__ bv_w, const float* __restrict__ bv_b) {
    __shared__ float sh[HID];
    int mat = blockIdx.x, b = blockIdx.y;
    const float* W; const float* bs;
    switch (mat) {
        case 0: W = gq_w; bs = gq_b; break;
        case 1: W = bq_w; bs = bq_b; break;
        case 2: W = gk_w; bs = gk_b; break;
        case 3: W = bk_w; bs = bk_b; break;
        case 4: W = gv_w; bs = gv_b; break;
        default: W = bv_w; bs = bv_b; break;
    }
    float* out = g_film + (mat * BB + b) * INNER;
    int t = threadIdx.x, wp = t >> 5, l = t & 31;
    if (t < HID) sh[t] = g_hm[b * HID + t];
    __syncthreads();
    float h0 = sh[l], h1 = sh[l + 32], h2 = sh[l + 64], h3 = sh[l + 96];
    for (int k = 0; k < 32; k++) {
        int o = wp * 32 + k;
        const float* wr = W + o * HID;
        float p = h0 * wr[l] + h1 * wr[l + 32] + h2 * wr[l + 64] + h3 * wr[l + 96];
#pragma unroll
        for (int off = 16; off > 0; off >>= 1) p += __shfl_xor_sync(0xffffffffu, p, off);
        if (l == 0) out[o] = p + __ldg(&bs[o]);
    }
}

// ---------------- K5: QKV GEMM + FiLM, token-major tf32 output ----------------
__global__ void __launch_bounds__(256) qkv_kernel(
    const float* __restrict__ x,
    const float* __restrict__ wq, const float* __restrict__ bq,
    const float* __restrict__ wk, const float* __restrict__ bk,
    const float* __restrict__ wv, const float* __restrict__ bv) {
    __shared__ float sW[32 * 128];
    __shared__ float sX[32 * 128];
    int which = blockIdx.z % 3;
    int b = blockIdx.z / 3;
    const float* W; const float* wb; const float* gvec; const float* bvec; float* out;
    if (which == 0) { W = wq; wb = bq; gvec = g_film + (0 * BB + b) * INNER; bvec = g_film + (1 * BB + b) * INNER; out = g_q; }
    else if (which == 1) { W = wk; wb = bk; gvec = g_film + (2 * BB + b) * INNER; bvec = g_film + (3 * BB + b) * INNER; out = g_k; }
    else { W = wv; wb = bv; gvec = g_film + (4 * BB + b) * INNER; bvec = g_film + (5 * BB + b) * INNER; out = g_v; }

    int o0 = blockIdx.y * 128, n0 = blockIdx.x * 128;
    int t = threadIdx.x;
    int r = t >> 4, cc = t & 15;
    u64 acc2[8][4];
#pragma unroll
    for (int i = 0; i < 8; i++)
#pragma unroll
        for (int j = 0; j < 4; j++) acc2[i][j] = 0ull;

    const float* xb = x + b * CCH * NN;
    const float4* sW4 = (const float4*)sW;
    const ulonglong2* sX2 = (const ulonglong2*)sX;
    for (int c0 = 0; c0 < CCH; c0 += 32) {
        __syncthreads();
        {
            int orow = t >> 1;
            int ckb = (t & 1) * 16;
            const float4* s4 = (const float4*)(W + (o0 + orow) * CCH + c0 + ckb);
            float4 v0 = s4[0], v1 = s4[1], v2 = s4[2], v3 = s4[3];
            float tmp[16] = {v0.x, v0.y, v0.z, v0.w, v1.x, v1.y, v1.z, v1.w,
                             v2.x, v2.y, v2.z, v2.w, v3.x, v3.y, v3.z, v3.w};
#pragma unroll
            for (int s = 0; s < 16; s++) sW[(ckb + s) * 128 + orow] = tmp[s];
        }
        {
            int row = t >> 3, cb = (t & 7) * 16;
            const float4* s4 = (const float4*)(xb + (c0 + row) * NN + n0 + cb);
            float4* d4 = (float4*)(sX + row * 128 + cb);
            d4[0] = s4[0]; d4[1] = s4[1]; d4[2] = s4[2]; d4[3] = s4[3];
        }
        __syncthreads();
#pragma unroll 4
        for (int ck = 0; ck < 32; ck++) {
            float4 wA = sW4[ck * 32 + r * 2], wB = sW4[ck * 32 + r * 2 + 1];
            ulonglong2 xA = sX2[ck * 32 + cc], xB = sX2[ck * 32 + 16 + cc];
            float wvv[8] = {wA.x, wA.y, wA.z, wA.w, wB.x, wB.y, wB.z, wB.w};
#pragma unroll
            for (int i = 0; i < 8; i++) {
                u64 w2; SPLAT2(w2, wvv[i]);
                FMA2(acc2[i][0], w2, xA.x);
                FMA2(acc2[i][1], w2, xA.y);
                FMA2(acc2[i][2], w2, xB.x);
                FMA2(acc2[i][3], w2, xB.y);
            }
        }
    }
#pragma unroll
    for (int i = 0; i < 8; i++) {
        int o = o0 + r * 8 + i;
        int h = o >> 5, d = o & 31;
        float gg = gvec[o], bb2 = bvec[o], wbb = wb[o];
        float a[8];
        UNPACK2(a[0], a[1], acc2[i][0]);
        UNPACK2(a[2], a[3], acc2[i][1]);
        UNPACK2(a[4], a[5], acc2[i][2]);
        UNPACK2(a[6], a[7], acc2[i][3]);
        float* ob = out + ((size_t)(b * NHEADS + h) * NN) * DHD + d;
#pragma unroll
        for (int j = 0; j < 8; j++) {
            int tok = n0 + ((j < 4) ? 0 : 64) + cc * 4 + (j & 3);
            float vfin = gg * (a[j] + wbb) + bb2;
            unsigned tf; CVT_TF32(tf, vfin);
            ob[(size_t)tok * DHD] = __uint_as_float(tf);
        }
    }
}

// ---------------- K6: flash attention, tf32 mma.sync ----------------
#define QP 36
#define VP 40
#define PP 132
extern __shared__ float smA[];
__global__ void __launch_bounds__(256) attn_kernel() {
    float* sQ = smA;                   // 128*36
    float* sK = sQ + 128 * QP;         // 128*36
    float* sV = sK + 128 * QP;         // 128*40
    float* sP = sV + 128 * VP;         // 128*132
    float* sBias = sP + 128 * PP;      // 128

    int bh = blockIdx.y;
    int b = bh >> 3, h = bh & 7;
    int qt0 = blockIdx.x * 128;
    int t = threadIdx.x;
    int w = t >> 5, lane = t & 31, g = lane >> 2, tg = lane & 3;
    int q0 = w * 16;

    const float* gq = g_q + (size_t)bh * NN * DHD;
    const float* gk = g_k + (size_t)bh * NN * DHD;
    const float* gv = g_v + (size_t)bh * NN * DHD;
    const float* biasb = g_bias + b * NN;

    // load Q tile [128 tok][32 d]
#pragma unroll
    for (int kk = 0; kk < 4; kk++) {
        int idx = t + kk * 256;
        int tok = idx >> 3, dv = (idx & 7) * 4;
        *(float4*)(sQ + tok * QP + dv) = *(const float4*)(gq + (size_t)(qt0 + tok) * DHD + dv);
    }

    float m0s = -1e30f, m1s = -1e30f, l0 = 0.f, l1 = 0.f;
    float o[4][4];
#pragma unroll
    for (int i = 0; i < 4; i++)
#pragma unroll
        for (int j = 0; j < 4; j++) o[i][j] = 0.f;

    for (int kt = 0; kt < 18; kt++) {
        int mt0 = kt * 128;
        __syncthreads();
#pragma unroll
        for (int kk = 0; kk < 4; kk++) {
            int idx = t + kk * 256;
            int tok = idx >> 3, dv = (idx & 7) * 4;
            *(float4*)(sK + tok * QP + dv) = *(const float4*)(gk + (size_t)(mt0 + tok) * DHD + dv);
            *(float4*)(sV + tok * VP + dv) = *(const float4*)(gv + (size_t)(mt0 + tok) * DHD + dv);
        }
        if (t < 128) sBias[t] = biasb[mt0 + t];
        __syncthreads();

        // ---- S = Q K^T via mma (warp: rows q0..q0+15, all 128 m) ----
        float c[16][4];
#pragma unroll
        for (int nt = 0; nt < 16; nt++)
#pragma unroll
            for (int j = 0; j < 4; j++) c[nt][j] = 0.f;
#pragma unroll
        for (int kc = 0; kc < 4; kc++) {
            int d0 = kc * 8;
            unsigned a0 = __float_as_uint(sQ[(q0 + g) * QP + d0 + tg]);
            unsigned a1 = __float_as_uint(sQ[(q0 + g + 8) * QP + d0 + tg]);
            unsigned a2 = __float_as_uint(sQ[(q0 + g) * QP + d0 + tg + 4]);
            unsigned a3 = __float_as_uint(sQ[(q0 + g + 8) * QP + d0 + tg + 4]);
#pragma unroll
            for (int nt = 0; nt < 16; nt++) {
                unsigned b0 = __float_as_uint(sK[(nt * 8 + g) * QP + d0 + tg]);
                unsigned b1 = __float_as_uint(sK[(nt * 8 + g) * QP + d0 + tg + 4]);
                MMA_TF32(c[nt][0], c[nt][1], c[nt][2], c[nt][3], a0, a1, a2, a3, b0, b1);
            }
        }

        // ---- scale + bias + rowmax ----
        float mx0 = -1e30f, mx1 = -1e30f;
#pragma unroll
        for (int nt = 0; nt < 16; nt++) {
            float bc0 = sBias[nt * 8 + 2 * tg], bc1 = sBias[nt * 8 + 2 * tg + 1];
            c[nt][0] = c[nt][0] * ATT_SCALE + bc0;
            c[nt][1] = c[nt][1] * ATT_SCALE + bc1;
            c[nt][2] = c[nt][2] * ATT_SCALE + bc0;
            c[nt][3] = c[nt][3] * ATT_SCALE + bc1;
            mx0 = fmaxf(mx0, fmaxf(c[nt][0], c[nt][1]));
            mx1 = fmaxf(mx1, fmaxf(c[nt][2], c[nt][3]));
        }
        mx0 = fmaxf(mx0, __shfl_xor_sync(0xffffffffu, mx0, 1));
        mx0 = fmaxf(mx0, __shfl_xor_sync(0xffffffffu, mx0, 2));
        mx1 = fmaxf(mx1, __shfl_xor_sync(0xffffffffu, mx1, 1));
        mx1 = fmaxf(mx1, __shfl_xor_sync(0xffffffffu, mx1, 2));
        float nm0 = fmaxf(m0s, mx0), nm1 = fmaxf(m1s, mx1);
        float sc0 = __expf(m0s - nm0), sc1 = __expf(m1s - nm1);
        m0s = nm0; m1s = nm1;

        float ts0 = 0.f, ts1 = 0.f;
#pragma unroll
        for (int nt = 0; nt < 16; nt++) {
            float p0 = __expf(c[nt][0] - nm0), p1 = __expf(c[nt][1] - nm0);
            float p2 = __expf(c[nt][2] - nm1), p3 = __expf(c[nt][3] - nm1);
            ts0 += p0 + p1; ts1 += p2 + p3;
            unsigned u0, u1, u2, u3;
            CVT_TF32(u0, p0); CVT_TF32(u1, p1); CVT_TF32(u2, p2); CVT_TF32(u3, p3);
            *(float2*)(sP + (q0 + g) * PP + nt * 8 + 2 * tg) =
                make_float2(__uint_as_float(u0), __uint_as_float(u1));
            *(float2*)(sP + (q0 + g + 8) * PP + nt * 8 + 2 * tg) =
                make_float2(__uint_as_float(u2), __uint_as_float(u3));
        }
        ts0 += __shfl_xor_sync(0xffffffffu, ts0, 1);
        ts0 += __shfl_xor_sync(0xffffffffu, ts0, 2);
        ts1 += __shfl_xor_sync(0xffffffffu, ts1, 1);
        ts1 += __shfl_xor_sync(0xffffffffu, ts1, 2);
        l0 = l0 * sc0 + ts0;
        l1 = l1 * sc1 + ts1;
#pragma unroll
        for (int ntd = 0; ntd < 4; ntd++) {
            o[ntd][0] *= sc0; o[ntd][1] *= sc0;
            o[ntd][2] *= sc1; o[ntd][3] *= sc1;
        }
        __syncwarp();

        // ---- O += P V (A = P rows q0.., B = V[m][d]) ----
#pragma unroll 4
        for (int kc = 0; kc < 16; kc++) {
            int mk = kc * 8;
            unsigned a0 = __float_as_uint(sP[(q0 + g) * PP + mk + tg]);
            unsigned a1 = __float_as_uint(sP[(q0 + g + 8) * PP + mk + tg]);
            unsigned a2 = __float_as_uint(sP[(q0 + g) * PP + mk + tg + 4]);
            unsigned a3 = __float_as_uint(sP[(q0 + g + 8) * PP + mk + tg + 4]);
#pragma unroll
            for (int ntd = 0; ntd < 4; ntd++) {
                unsigned b0 = __float_as_uint(sV[(mk + tg) * VP + ntd * 8 + g]);
                unsigned b1 = __float_as_uint(sV[(mk + tg + 4) * VP + ntd * 8 + g]);
                MMA_TF32(o[ntd][0], o[ntd][1], o[ntd][2], o[ntd][3], a0, a1, a2, a3, b0, b1);
            }
        }
    }

    // ---- epilogue: normalize, transpose via smem, coalesced store ----
    __syncthreads();
    float il0 = 1.f / l0, il1 = 1.f / l1;
#pragma unroll
    for (int ntd = 0; ntd < 4; ntd++) {
        int d0 = ntd * 8 + 2 * tg;
        sP[d0 * PP + q0 + g] = o[ntd][0] * il0;
        sP[(d0 + 1) * PP + q0 + g] = o[ntd][1] * il0;
        sP[d0 * PP + q0 + g + 8] = o[ntd][2] * il1;
        sP[(d0 + 1) * PP + q0 + g + 8] = o[ntd][3] * il1;
    }
    __syncthreads();
    float* gO = g_O + ((size_t)b * INNER + h * DHD) * NN;
#pragma unroll
    for (int kk = 0; kk < 4; kk++) {
        int idx = t + kk * 256;
        int d = idx >> 5, q4 = (idx & 31) * 4;
        *(float4*)(gO + (size_t)d * NN + qt0 + q4) = *(float4*)(sP + d * PP + q4);
    }
}

// ---------------- K7: output projection GEMM (FFMA2) ----------------
__global__ void __launch_bounds__(256) proj_kernel(
    const float* __restrict__ W, const float* __restrict__ wb, float* __restrict__ out0) {
    __shared__ float sW[32 * 128];
    __shared__ float sX[32 * 128];
    int b = blockIdx.z;
    const float* X = g_O + (size_t)b * INNER * NN;
    float* out = out0 + (size_t)b * CCH * NN;
    int o0 = blockIdx.y * 128, n0 = blockIdx.x * 128;
    int t = threadIdx.x;
    int r = t >> 4, cc = t & 15;
    u64 acc2[8][4];
#pragma unroll
    for (int i = 0; i < 8; i++)
#pragma unroll
        for (int j = 0; j < 4; j++) acc2[i][j] = 0ull;

    const float4* sW4 = (const float4*)sW;
    const ulonglong2* sX2 = (const ulonglong2*)sX;
    for (int c0 = 0; c0 < INNER; c0 += 32) {
        __syncthreads();
        {
            int orow = t >> 1;
            int ckb = (t & 1) * 16;
            const float4* s4 = (const float4*)(W + (o0 + orow) * INNER + c0 + ckb);
            float4 v0 = s4[0], v1 = s4[1], v2 = s4[2], v3 = s4[3];
            float tmp[16] = {v0.x, v0.y, v0.z, v0.w, v1.x, v1.y, v1.z, v1.w,
                             v2.x, v2.y, v2.z, v2.w, v3.x, v3.y, v3.z, v3.w};
#pragma unroll
            for (int s = 0; s < 16; s++) sW[(ckb + s) * 128 + orow] = tmp[s];
        }
        {
            int row = t >> 3, cb = (t & 7) * 16;
            const float4* s4 = (const float4*)(X + (size_t)(c0 + row) * NN + n0 + cb);
            float4* d4 = (float4*)(sX + row * 128 + cb);
            d4[0] = s4[0]; d4[1] = s4[1]; d4[2] = s4[2]; d4[3] = s4[3];
        }
        __syncthreads();
#pragma unroll 4
        for (int ck = 0; ck < 32; ck++) {
            float4 wA = sW4[ck * 32 + r * 2], wB = sW4[ck * 32 + r * 2 + 1];
            ulonglong2 xA = sX2[ck * 32 + cc], xB = sX2[ck * 32 + 16 + cc];
            float wvv[8] = {wA.x, wA.y, wA.z, wA.w, wB.x, wB.y, wB.z, wB.w};
#pragma unroll
            for (int i = 0; i < 8; i++) {
                u64 w2; SPLAT2(w2, wvv[i]);
                FMA2(acc2[i][0], w2, xA.x);
                FMA2(acc2[i][1], w2, xA.y);
                FMA2(acc2[i][2], w2, xB.x);
                FMA2(acc2[i][3], w2, xB.y);
            }
        }
    }
#pragma unroll
    for (int i = 0; i < 8; i++) {
        int o = o0 + r * 8 + i;
        float bb2 = wb[o];
        float a[8];
        UNPACK2(a[0], a[1], acc2[i][0]);
        UNPACK2(a[2], a[3], acc2[i][1]);
        UNPACK2(a[4], a[5], acc2[i][2]);
        UNPACK2(a[6], a[7], acc2[i][3]);
        float4 vA = make_float4(a[0] + bb2, a[1] + bb2, a[2] + bb2, a[3] + bb2);
        float4 vB = make_float4(a[4] + bb2, a[5] + bb2, a[6] + bb2, a[7] + bb2);
        *(float4*)(out + (size_t)o * NN + n0 + cc * 4) = vA;
        *(float4*)(out + (size_t)o * NN + n0 + 64 + cc * 4) = vB;
    }
}

// ---------------- launch ----------------
extern "C" void kernel_launch(void* const* d_in, const int* in_sizes, int n_in,
                              void* d_out, int out_size) {
    const float* x      = (const float*)d_in[0];
    const float* rgb    = (const float*)d_in[1];
    const float* wq     = (const float*)d_in[2];
    const float* bq     = (const float*)d_in[3];
    const float* wk     = (const float*)d_in[4];
    const float* bk     = (const float*)d_in[5];
    const float* wv     = (const float*)d_in[6];
    const float* bv     = (const float*)d_in[7];
    const float* wproj  = (const float*)d_in[8];
    const float* bproj  = (const float*)d_in[9];
    const float* c1_w   = (const float*)d_in[10];
    const float* c1_b   = (const float*)d_in[11];
    const float* c2_w   = (const float*)d_in[12];
    const float* c2_b   = (const float*)d_in[13];
    const float* gq_w   = (const float*)d_in[14];
    const float* gq_b   = (const float*)d_in[15];
    const float* bqf_w  = (const float*)d_in[16];
    const float* bqf_b  = (const float*)d_in[17];
    const float* gk_w   = (const float*)d_in[18];
    const float* gk_b   = (const float*)d_in[19];
    const float* bkf_w  = (const float*)d_in[20];
    const float* bkf_b  = (const float*)d_in[21];
    const float* gv_w   = (const float*)d_in[22];
    const float* gv_b   = (const float*)d_in[23];
    const float* bvf_w  = (const float*)d_in[24];
    const float* bvf_b  = (const float*)d_in[25];
    const float* alpha  = (const float*)d_in[26];

    luma_kernel<<<BB, 256>>>(rgb, alpha);
    conv1_kernel<<<dim3(8, BB), 256>>>(c1_w, c1_b);
    conv2_kernel<<<dim3(32, BB), 256>>>(c2_w, c2_b);
    film_kernel<<<dim3(6, BB), 256>>>(gq_w, gq_b, bqf_w, bqf_b, gk_w, gk_b, bkf_w, bkf_b,
                                      gv_w, gv_b, bvf_w, bvf_b);
    qkv_kernel<<<dim3(18, 2, 12), 256>>>(x, wq, bq, wk, bk, wv, bv);

    const int ATTN_SMEM = (128 * QP * 2 + 128 * VP + 128 * PP + 128) * 4;  // 125,440 B
    cudaFuncSetAttribute(attn_kernel, cudaFuncAttributeMaxDynamicSharedMemorySize, ATTN_SMEM);
    attn_kernel<<<dim3(18, 32), 256, ATTN_SMEM>>>();

    proj_kernel<<<dim3(18, 2, 4), 256>>>(wproj, bproj, (float*)d_out);
}

// round 5
// speedup vs baseline: 1.9534x; 1.0522x over previous
#include <cuda_runtime.h>

#define BB 4
#define CCH 256
#define HH 48
#define NN 2304
#define NHEADS 8
#define DHD 32
#define INNER 256
#define HID 128
#define ATT_SCALE 0.17677669529663687f
#define EPSV 1e-6f

// ---------- packed f32x2 helpers ----------
#define FMA2(acc, a, b)  asm("fma.rn.f32x2 %0, %1, %2, %0;" : "+l"(acc) : "l"(a), "l"(b))
#define SPLAT2(d, f)     asm("mov.b64 %0, {%1, %1};" : "=l"(d) : "f"(f))
#define PACK2(d, lo, hi) asm("mov.b64 %0, {%1, %2};" : "=l"(d) : "f"(lo), "f"(hi))
#define UNPACK2(lo, hi, v) asm("mov.b64 {%0, %1}, %2;" : "=f"(lo), "=f"(hi) : "l"(v))
typedef unsigned long long u64;

// ---------- tf32 helpers ----------
#define CVT_TF32(d, f) asm("cvt.rna.tf32.f32 %0, %1;" : "=r"(d) : "f"(f))
#define MMA_TF32(c0,c1,c2,c3,a0,a1,a2,a3,b0,b1) \
  asm volatile("mma.sync.aligned.m16n8k8.row.col.f32.tf32.tf32.f32 " \
      "{%0,%1,%2,%3}, {%4,%5,%6,%7}, {%8,%9}, {%0,%1,%2,%3};" \
      : "+f"(c0), "+f"(c1), "+f"(c2), "+f"(c3) \
      : "r"(a0), "r"(a1), "r"(a2), "r"(a3), "r"(b0), "r"(b1))

__device__ __forceinline__ void split_tf32(float v, float& hi, float& lo) {
    unsigned uh; CVT_TF32(uh, v);
    hi = __uint_as_float(uh);
    float d = v - hi;
    unsigned ul; CVT_TF32(ul, d);
    lo = __uint_as_float(ul);
}

// ---------------- scratch ----------------
__device__ float g_luma[BB * NN];
__device__ float g_bias[BB * NN];
__device__ float g_h1[BB * HID * NN];
__device__ float g_hm[BB * HID];
__device__ float g_film[6 * BB * INNER];
__device__ float g_q[BB * NHEADS * NN * DHD];   // token-major [B,H,N,32], tf32-rounded
__device__ float g_k[BB * NHEADS * NN * DHD];
__device__ float g_v[BB * NHEADS * NN * DHD];
__device__ float g_O[BB * NHEADS * NN * DHD];   // token-major [B,H,N,32]

// ---------------- K1: luma + normalization + pooled bias ----------------
__global__ void luma_kernel(const float* __restrict__ rgb, const float* __restrict__ alphap) {
    __shared__ float sPad[50 * 50];
    __shared__ float red[256];
    int b = blockIdx.x;
    int t = threadIdx.x;
    for (int i = t; i < 2500; i += 256) sPad[i] = 0.f;

    const float* rp = rgb + b * 3 * NN;
    float y[9];
    float mn = 1e30f, mx = -1e30f;
#pragma unroll
    for (int k = 0; k < 9; k++) {
        int p = t + k * 256;
        float yy = 0.299f * rp[p] + 0.587f * rp[NN + p] + 0.114f * rp[2 * NN + p];
        y[k] = yy;
        mn = fminf(mn, yy);
        mx = fmaxf(mx, yy);
    }
    red[t] = mn; __syncthreads();
    for (int s = 128; s > 0; s >>= 1) { if (t < s) red[t] = fminf(red[t], red[t + s]); __syncthreads(); }
    mn = red[0]; __syncthreads();
    red[t] = mx; __syncthreads();
    for (int s = 128; s > 0; s >>= 1) { if (t < s) red[t] = fmaxf(red[t], red[t + s]); __syncthreads(); }
    mx = red[0]; __syncthreads();

    float inv = 1.f / (mx - mn + EPSV);
#pragma unroll
    for (int k = 0; k < 9; k++) {
        int p = t + k * 256;
        float ln = (y[k] - mn) * inv;
        g_luma[b * NN + p] = ln;
        sPad[(p / 48 + 1) * 50 + (p % 48) + 1] = 1.f - ln;
    }
    __syncthreads();

    float pooled[9];
    float ls = 0.f;
#pragma unroll
    for (int k = 0; k < 9; k++) {
        int p = t + k * 256;
        int base = (p / 48) * 50 + (p % 48);
        float s0 = 0.f;
#pragma unroll
        for (int a = 0; a < 3; a++)
#pragma unroll
            for (int c2 = 0; c2 < 3; c2++) s0 += sPad[base + a * 50 + c2];
        s0 *= (1.f / 9.f);
        pooled[k] = s0;
        ls += s0;
    }
    red[t] = ls; __syncthreads();
    for (int s = 128; s > 0; s >>= 1) { if (t < s) red[t] += red[t + s]; __syncthreads(); }
    float mean = red[0] * (1.f / 2304.f);
    float alpha = *alphap;
#pragma unroll
    for (int k = 0; k < 9; k++) {
        int p = t + k * 256;
        g_bias[b * NN + p] = alpha * (pooled[k] - mean);
    }
}

// ---------------- K2: conv1 ----------------
__global__ void __launch_bounds__(256) conv1_kernel(const float* __restrict__ w, const float* __restrict__ bias) {
    __shared__ float sPad[2500];
    int b = blockIdx.y, ocg = blockIdx.x * 16;
    int t = threadIdx.x;
    for (int i = t; i < 2500; i += 256) sPad[i] = 0.f;
    __syncthreads();
    const float* src = g_luma + b * NN;
    for (int i = t; i < NN; i += 256) sPad[(i / 48 + 1) * 50 + (i % 48) + 1] = src[i];
    __syncthreads();
    int py = (t >> 4) * 3, px = (t & 15) * 3;
    float nb[5][5];
#pragma unroll
    for (int a = 0; a < 5; a++)
#pragma unroll
        for (int c2 = 0; c2 < 5; c2++) nb[a][c2] = sPad[(py + a) * 50 + px + c2];

    for (int o = 0; o < 16; o++) {
        int oc = ocg + o;
        float wv[9];
#pragma unroll
        for (int k = 0; k < 9; k++) wv[k] = __ldg(&w[oc * 9 + k]);
        float bb = __ldg(&bias[oc]);
        float* dst = g_h1 + (b * HID + oc) * NN;
#pragma unroll
        for (int i = 0; i < 3; i++)
#pragma unroll
            for (int j = 0; j < 3; j++) {
                float a0 = bb;
#pragma unroll
                for (int ky = 0; ky < 3; ky++)
#pragma unroll
                    for (int kx = 0; kx < 3; kx++) a0 += wv[ky * 3 + kx] * nb[i + ky][j + kx];
                dst[(py + i) * 48 + px + j] = fmaxf(a0, 0.f);
            }
    }
}

// ---------------- K3: conv2 (FFMA2, 4 oc per block) ----------------
__global__ void __launch_bounds__(256) conv2_kernel(const float* __restrict__ w, const float* __restrict__ bias) {
    __shared__ float sPad[2500];
    __shared__ u64 sW2[1152 * 2];
    __shared__ float red[256];
    int b = blockIdx.y, ocg = blockIdx.x * 4;
    int t = threadIdx.x;
    for (int i = t; i < 2500; i += 256) sPad[i] = 0.f;
    for (int idx = t; idx < 2304; idx += 256) {
        int pair = idx & 1, wi = idx >> 1;
        int oc = ocg + pair * 2;
        float lo = __ldg(&w[oc * 1152 + wi]);
        float hi = __ldg(&w[(oc + 1) * 1152 + wi]);
        u64 pk; PACK2(pk, lo, hi);
        sW2[idx] = pk;
    }
    int sidx[9];
#pragma unroll
    for (int k = 0; k < 9; k++) { int p = t + k * 256; sidx[k] = (p / 48 + 1) * 50 + (p % 48) + 1; }
    int py = (t >> 4) * 3, px = (t & 15) * 3;

    u64 bias0, bias1;
    PACK2(bias0, __ldg(&bias[ocg]), __ldg(&bias[ocg + 1]));
    PACK2(bias1, __ldg(&bias[ocg + 2]), __ldg(&bias[ocg + 3]));
    u64 acc2[2][9];
#pragma unroll
    for (int k = 0; k < 9; k++) { acc2[0][k] = bias0; acc2[1][k] = bias1; }

    for (int ic = 0; ic < HID; ic++) {
        __syncthreads();
        const float* src = g_h1 + (b * HID + ic) * NN;
#pragma unroll
        for (int k = 0; k < 9; k++) sPad[sidx[k]] = src[t + k * 256];
        __syncthreads();
        float nb[5][5];
#pragma unroll
        for (int a = 0; a < 5; a++)
#pragma unroll
            for (int c2 = 0; c2 < 5; c2++) nb[a][c2] = sPad[(py + a) * 50 + px + c2];
        const u64* wrow = sW2 + ic * 18;
#pragma unroll
        for (int ky = 0; ky < 3; ky++)
#pragma unroll
            for (int kx = 0; kx < 3; kx++) {
                int tap = ky * 3 + kx;
                u64 w0 = wrow[tap * 2], w1 = wrow[tap * 2 + 1];
#pragma unroll
                for (int i = 0; i < 3; i++)
#pragma unroll
                    for (int j = 0; j < 3; j++) {
                        u64 nb2; SPLAT2(nb2, nb[i + ky][j + kx]);
                        FMA2(acc2[0][i * 3 + j], nb2, w0);
                        FMA2(acc2[1][i * 3 + j], nb2, w1);
                    }
            }
    }
    float ls[4] = {0.f, 0.f, 0.f, 0.f};
#pragma unroll
    for (int k = 0; k < 9; k++) {
        float v0, v1, v2, v3;
        UNPACK2(v0, v1, acc2[0][k]);
        UNPACK2(v2, v3, acc2[1][k]);
        ls[0] += fmaxf(v0, 0.f); ls[1] += fmaxf(v1, 0.f);
        ls[2] += fmaxf(v2, 0.f); ls[3] += fmaxf(v3, 0.f);
    }
#pragma unroll
    for (int o4 = 0; o4 < 4; o4++) {
        __syncthreads();
        red[t] = ls[o4]; __syncthreads();
        for (int s = 128; s > 0; s >>= 1) { if (t < s) red[t] += red[t + s]; __syncthreads(); }
        if (t == 0) g_hm[b * HID + ocg + o4] = red[0] * (1.f / 2304.f);
    }
}

// ---------------- K4: FiLM params ----------------
__global__ void __launch_bounds__(256) film_kernel(
    const float* __restrict__ gq_w, const float* __restrict__ gq_b,
    const float* __restrict__ bq_w, const float* __restrict__ bq_b,
    const float* __restrict__ gk_w, const float* __restrict__ gk_b,
    const float* __restrict__ bk_w, const float* __restrict__ bk_b,
    const float* __restrict__ gv_w, const float* __restrict__ gv_b,
    const float* __restrict__ bv_w, const float* __restrict__ bv_b) {
    __shared__ float sh[HID];
    int mat = blockIdx.x, b = blockIdx.y;
    const float* W; const float* bs;
    switch (mat) {
        case 0: W = gq_w; bs = gq_b; break;
        case 1: W = bq_w; bs = bq_b; break;
        case 2: W = gk_w; bs = gk_b; break;
        case 3: W = bk_w; bs = bk_b; break;
        case 4: W = gv_w; bs = gv_b; break;
        default: W = bv_w; bs = bv_b; break;
    }
    float* out = g_film + (mat * BB + b) * INNER;
    int t = threadIdx.x, wp = t >> 5, l = t & 31;
    if (t < HID) sh[t] = g_hm[b * HID + t];
    __syncthreads();
    float h0 = sh[l], h1 = sh[l + 32], h2 = sh[l + 64], h3 = sh[l + 96];
    for (int k = 0; k < 32; k++) {
        int o = wp * 32 + k;
        const float* wr = W + o * HID;
        float p = h0 * wr[l] + h1 * wr[l + 32] + h2 * wr[l + 64] + h3 * wr[l + 96];
#pragma unroll
        for (int off = 16; off > 0; off >>= 1) p += __shfl_xor_sync(0xffffffffu, p, off);
        if (l == 0) out[o] = p + __ldg(&bs[o]);
    }
}

// ---------------- K5: QKV projection, 3xTF32 mma, token-major output ----------------
// C[tok][o] = sum_c X[c][tok] * W[o][c]
extern __shared__ float smQ[];
__global__ void __launch_bounds__(256) qkv_kernel(
    const float* __restrict__ x,
    const float* __restrict__ wq, const float* __restrict__ bq,
    const float* __restrict__ wk, const float* __restrict__ bk,
    const float* __restrict__ wv, const float* __restrict__ bv) {
    float* sXhi = smQ;                 // 128*36
    float* sXlo = sXhi + 128 * 36;
    float* sWhi = sXlo + 128 * 36;
    float* sWlo = sWhi + 128 * 36;
    int which = blockIdx.z % 3;
    int b = blockIdx.z / 3;
    const float* W; const float* wb; const float* gvec; const float* bvec; float* out;
    if (which == 0) { W = wq; wb = bq; gvec = g_film + (0 * BB + b) * INNER; bvec = g_film + (1 * BB + b) * INNER; out = g_q; }
    else if (which == 1) { W = wk; wb = bk; gvec = g_film + (2 * BB + b) * INNER; bvec = g_film + (3 * BB + b) * INNER; out = g_k; }
    else { W = wv; wb = bv; gvec = g_film + (4 * BB + b) * INNER; bvec = g_film + (5 * BB + b) * INNER; out = g_v; }

    int n0 = blockIdx.x * 128;   // token tile
    int o0 = blockIdx.y * 128;   // output-channel tile
    int t = threadIdx.x;
    int w = t >> 5, lane = t & 31, g = lane >> 2, tg = lane & 3;
    int q0 = w * 16;

    float c[16][4];
#pragma unroll
    for (int nt = 0; nt < 16; nt++)
#pragma unroll
        for (int j = 0; j < 4; j++) c[nt][j] = 0.f;

    const float* xb = x + (size_t)b * CCH * NN;
    for (int c0 = 0; c0 < CCH; c0 += 32) {
        __syncthreads();
        {   // X tile: gmem [c][n] -> smem [tok][c] hi/lo
            int cr = t >> 3, nblk = (t & 7) * 16;
            const float4* s4 = (const float4*)(xb + (size_t)(c0 + cr) * NN + n0 + nblk);
#pragma unroll
            for (int j = 0; j < 4; j++) {
                float4 v = s4[j];
                int tk = nblk + j * 4;
                float vh, vl;
                split_tf32(v.x, vh, vl); sXhi[(tk + 0) * 36 + cr] = vh; sXlo[(tk + 0) * 36 + cr] = vl;
                split_tf32(v.y, vh, vl); sXhi[(tk + 1) * 36 + cr] = vh; sXlo[(tk + 1) * 36 + cr] = vl;
                split_tf32(v.z, vh, vl); sXhi[(tk + 2) * 36 + cr] = vh; sXlo[(tk + 2) * 36 + cr] = vl;
                split_tf32(v.w, vh, vl); sXhi[(tk + 3) * 36 + cr] = vh; sXlo[(tk + 3) * 36 + cr] = vl;
            }
        }
        {   // W tile: gmem [o][c] -> smem [o][c] hi/lo
            int orow = t >> 1, cpart = (t & 1) * 16;
            const float4* s4 = (const float4*)(W + (size_t)(o0 + orow) * CCH + c0 + cpart);
#pragma unroll
            for (int j = 0; j < 4; j++) {
                float4 v = s4[j];
                int cidx = cpart + j * 4;
                float vh, vl;
                split_tf32(v.x, vh, vl); sWhi[orow * 36 + cidx + 0] = vh; sWlo[orow * 36 + cidx + 0] = vl;
                split_tf32(v.y, vh, vl); sWhi[orow * 36 + cidx + 1] = vh; sWlo[orow * 36 + cidx + 1] = vl;
                split_tf32(v.z, vh, vl); sWhi[orow * 36 + cidx + 2] = vh; sWlo[orow * 36 + cidx + 2] = vl;
                split_tf32(v.w, vh, vl); sWhi[orow * 36 + cidx + 3] = vh; sWlo[orow * 36 + cidx + 3] = vl;
            }
        }
        __syncthreads();
#pragma unroll
        for (int kc = 0; kc < 4; kc++) {
            int k0 = kc * 8;
            unsigned ah0 = __float_as_uint(sXhi[(q0 + g) * 36 + k0 + tg]);
            unsigned ah1 = __float_as_uint(sXhi[(q0 + g + 8) * 36 + k0 + tg]);
            unsigned ah2 = __float_as_uint(sXhi[(q0 + g) * 36 + k0 + tg + 4]);
            unsigned ah3 = __float_as_uint(sXhi[(q0 + g + 8) * 36 + k0 + tg + 4]);
            unsigned al0 = __float_as_uint(sXlo[(q0 + g) * 36 + k0 + tg]);
            unsigned al1 = __float_as_uint(sXlo[(q0 + g + 8) * 36 + k0 + tg]);
            unsigned al2 = __float_as_uint(sXlo[(q0 + g) * 36 + k0 + tg + 4]);
            unsigned al3 = __float_as_uint(sXlo[(q0 + g + 8) * 36 + k0 + tg + 4]);
#pragma unroll
            for (int nt = 0; nt < 16; nt++) {
                unsigned bh0 = __float_as_uint(sWhi[(nt * 8 + g) * 36 + k0 + tg]);
                unsigned bh1 = __float_as_uint(sWhi[(nt * 8 + g) * 36 + k0 + tg + 4]);
                unsigned bl0 = __float_as_uint(sWlo[(nt * 8 + g) * 36 + k0 + tg]);
                unsigned bl1 = __float_as_uint(sWlo[(nt * 8 + g) * 36 + k0 + tg + 4]);
                MMA_TF32(c[nt][0], c[nt][1], c[nt][2], c[nt][3], ah0, ah1, ah2, ah3, bh0, bh1);
                MMA_TF32(c[nt][0], c[nt][1], c[nt][2], c[nt][3], ah0, ah1, ah2, ah3, bl0, bl1);
                MMA_TF32(c[nt][0], c[nt][1], c[nt][2], c[nt][3], al0, al1, al2, al3, bh0, bh1);
            }
        }
    }

    // epilogue: FiLM + tf32 round + token-major float2 stores
    int tok0 = n0 + q0 + g;
#pragma unroll
    for (int nt = 0; nt < 16; nt++) {
        int o = o0 + nt * 8 + 2 * tg;
        int h = o >> 5, d = o & 31;
        float g0 = __ldg(&gvec[o]),     bt0 = __ldg(&bvec[o]),     w0 = __ldg(&wb[o]);
        float g1 = __ldg(&gvec[o + 1]), bt1 = __ldg(&bvec[o + 1]), w1 = __ldg(&wb[o + 1]);
        float v0 = g0 * (c[nt][0] + w0) + bt0;
        float v1 = g1 * (c[nt][1] + w1) + bt1;
        float v2 = g0 * (c[nt][2] + w0) + bt0;
        float v3 = g1 * (c[nt][3] + w1) + bt1;
        unsigned u0, u1, u2, u3;
        CVT_TF32(u0, v0); CVT_TF32(u1, v1); CVT_TF32(u2, v2); CVT_TF32(u3, v3);
        float* ob = out + ((size_t)(b * NHEADS + h) * NN) * DHD + d;
        *(float2*)(ob + (size_t)tok0 * DHD) = make_float2(__uint_as_float(u0), __uint_as_float(u1));
        *(float2*)(ob + (size_t)(tok0 + 8) * DHD) = make_float2(__uint_as_float(u2), __uint_as_float(u3));
    }
}

// ---------------- K6: flash attention, tf32 mma.sync ----------------
#define QP 36
#define VP 40
#define PP 132
extern __shared__ float smA[];
__global__ void __launch_bounds__(256) attn_kernel() {
    float* sQ = smA;                   // 128*36
    float* sK = sQ + 128 * QP;         // 128*36
    float* sV = sK + 128 * QP;         // 128*40
    float* sP = sV + 128 * VP;         // 128*132
    float* sBias = sP + 128 * PP;      // 128

    int bh = blockIdx.y;
    int b = bh >> 3;
    int qt0 = blockIdx.x * 128;
    int t = threadIdx.x;
    int w = t >> 5, lane = t & 31, g = lane >> 2, tg = lane & 3;
    int q0 = w * 16;

    const float* gq = g_q + (size_t)bh * NN * DHD;
    const float* gk = g_k + (size_t)bh * NN * DHD;
    const float* gv = g_v + (size_t)bh * NN * DHD;
    const float* biasb = g_bias + b * NN;

#pragma unroll
    for (int kk = 0; kk < 4; kk++) {
        int idx = t + kk * 256;
        int tok = idx >> 3, dv = (idx & 7) * 4;
        *(float4*)(sQ + tok * QP + dv) = *(const float4*)(gq + (size_t)(qt0 + tok) * DHD + dv);
    }

    float m0s = -1e30f, m1s = -1e30f, l0 = 0.f, l1 = 0.f;
    float o[4][4];
#pragma unroll
    for (int i = 0; i < 4; i++)
#pragma unroll
        for (int j = 0; j < 4; j++) o[i][j] = 0.f;

    for (int kt = 0; kt < 18; kt++) {
        int mt0 = kt * 128;
        __syncthreads();
#pragma unroll
        for (int kk = 0; kk < 4; kk++) {
            int idx = t + kk * 256;
            int tok = idx >> 3, dv = (idx & 7) * 4;
            *(float4*)(sK + tok * QP + dv) = *(const float4*)(gk + (size_t)(mt0 + tok) * DHD + dv);
            *(float4*)(sV + tok * VP + dv) = *(const float4*)(gv + (size_t)(mt0 + tok) * DHD + dv);
        }
        if (t < 128) sBias[t] = biasb[mt0 + t];
        __syncthreads();

        float c[16][4];
#pragma unroll
        for (int nt = 0; nt < 16; nt++)
#pragma unroll
            for (int j = 0; j < 4; j++) c[nt][j] = 0.f;
#pragma unroll
        for (int kc = 0; kc < 4; kc++) {
            int d0 = kc * 8;
            unsigned a0 = __float_as_uint(sQ[(q0 + g) * QP + d0 + tg]);
            unsigned a1 = __float_as_uint(sQ[(q0 + g + 8) * QP + d0 + tg]);
            unsigned a2 = __float_as_uint(sQ[(q0 + g) * QP + d0 + tg + 4]);
            unsigned a3 = __float_as_uint(sQ[(q0 + g + 8) * QP + d0 + tg + 4]);
#pragma unroll
            for (int nt = 0; nt < 16; nt++) {
                unsigned b0 = __float_as_uint(sK[(nt * 8 + g) * QP + d0 + tg]);
                unsigned b1 = __float_as_uint(sK[(nt * 8 + g) * QP + d0 + tg + 4]);
                MMA_TF32(c[nt][0], c[nt][1], c[nt][2], c[nt][3], a0, a1, a2, a3, b0, b1);
            }
        }

        float mx0 = -1e30f, mx1 = -1e30f;
#pragma unroll
        for (int nt = 0; nt < 16; nt++) {
            float bc0 = sBias[nt * 8 + 2 * tg], bc1 = sBias[nt * 8 + 2 * tg + 1];
            c[nt][0] = c[nt][0] * ATT_SCALE + bc0;
            c[nt][1] = c[nt][1] * ATT_SCALE + bc1;
            c[nt][2] = c[nt][2] * ATT_SCALE + bc0;
            c[nt][3] = c[nt][3] * ATT_SCALE + bc1;
            mx0 = fmaxf(mx0, fmaxf(c[nt][0], c[nt][1]));
            mx1 = fmaxf(mx1, fmaxf(c[nt][2], c[nt][3]));
        }
        mx0 = fmaxf(mx0, __shfl_xor_sync(0xffffffffu, mx0, 1));
        mx0 = fmaxf(mx0, __shfl_xor_sync(0xffffffffu, mx0, 2));
        mx1 = fmaxf(mx1, __shfl_xor_sync(0xffffffffu, mx1, 1));
        mx1 = fmaxf(mx1, __shfl_xor_sync(0xffffffffu, mx1, 2));
        float nm0 = fmaxf(m0s, mx0), nm1 = fmaxf(m1s, mx1);
        float sc0 = __expf(m0s - nm0), sc1 = __expf(m1s - nm1);
        m0s = nm0; m1s = nm1;

        float ts0 = 0.f, ts1 = 0.f;
#pragma unroll
        for (int nt = 0; nt < 16; nt++) {
            float p0 = __expf(c[nt][0] - nm0), p1 = __expf(c[nt][1] - nm0);
            float p2 = __expf(c[nt][2] - nm1), p3 = __expf(c[nt][3] - nm1);
            ts0 += p0 + p1; ts1 += p2 + p3;
            unsigned u0, u1, u2, u3;
            CVT_TF32(u0, p0); CVT_TF32(u1, p1); CVT_TF32(u2, p2); CVT_TF32(u3, p3);
            *(float2*)(sP + (q0 + g) * PP + nt * 8 + 2 * tg) =
                make_float2(__uint_as_float(u0), __uint_as_float(u1));
            *(float2*)(sP + (q0 + g + 8) * PP + nt * 8 + 2 * tg) =
                make_float2(__uint_as_float(u2), __uint_as_float(u3));
        }
        ts0 += __shfl_xor_sync(0xffffffffu, ts0, 1);
        ts0 += __shfl_xor_sync(0xffffffffu, ts0, 2);
        ts1 += __shfl_xor_sync(0xffffffffu, ts1, 1);
        ts1 += __shfl_xor_sync(0xffffffffu, ts1, 2);
        l0 = l0 * sc0 + ts0;
        l1 = l1 * sc1 + ts1;
#pragma unroll
        for (int ntd = 0; ntd < 4; ntd++) {
            o[ntd][0] *= sc0; o[ntd][1] *= sc0;
            o[ntd][2] *= sc1; o[ntd][3] *= sc1;
        }
        __syncwarp();

#pragma unroll 4
        for (int kc = 0; kc < 16; kc++) {
            int mk = kc * 8;
            unsigned a0 = __float_as_uint(sP[(q0 + g) * PP + mk + tg]);
            unsigned a1 = __float_as_uint(sP[(q0 + g + 8) * PP + mk + tg]);
            unsigned a2 = __float_as_uint(sP[(q0 + g) * PP + mk + tg + 4]);
            unsigned a3 = __float_as_uint(sP[(q0 + g + 8) * PP + mk + tg + 4]);
#pragma unroll
            for (int ntd = 0; ntd < 4; ntd++) {
                unsigned b0 = __float_as_uint(sV[(mk + tg) * VP + ntd * 8 + g]);
                unsigned b1 = __float_as_uint(sV[(mk + tg + 4) * VP + ntd * 8 + g]);
                MMA_TF32(o[ntd][0], o[ntd][1], o[ntd][2], o[ntd][3], a0, a1, a2, a3, b0, b1);
            }
        }
    }

    // epilogue: normalize, direct token-major float2 stores
    float il0 = 1.f / l0, il1 = 1.f / l1;
    float* gO = g_O + (size_t)bh * NN * DHD;
    int tok0 = qt0 + q0 + g;
#pragma unroll
    for (int ntd = 0; ntd < 4; ntd++) {
        int d = ntd * 8 + 2 * tg;
        *(float2*)(gO + (size_t)tok0 * DHD + d) = make_float2(o[ntd][0] * il0, o[ntd][1] * il0);
        *(float2*)(gO + (size_t)(tok0 + 8) * DHD + d) = make_float2(o[ntd][2] * il1, o[ntd][3] * il1);
    }
}

// ---------------- K7: output projection, 3xTF32 mma ----------------
// C[o][n] = sum_c Wproj[o][c] * O[c][n]
extern __shared__ float smP[];
__global__ void __launch_bounds__(256) proj_kernel(
    const float* __restrict__ W, const float* __restrict__ wb, float* __restrict__ out0) {
    float* sWhi = smP;                 // 128*36
    float* sWlo = sWhi + 128 * 36;
    float* sXhi = sWlo + 128 * 36;
    float* sXlo = sXhi + 128 * 36;
    int b = blockIdx.z;
    float* out = out0 + (size_t)b * CCH * NN;
    int o0 = blockIdx.y * 128, n0 = blockIdx.x * 128;
    int t = threadIdx.x;
    int w = t >> 5, lane = t & 31, g = lane >> 2, tg = lane & 3;
    int q0 = w * 16;

    float c[16][4];
#pragma unroll
    for (int nt = 0; nt < 16; nt++)
#pragma unroll
        for (int j = 0; j < 4; j++) c[nt][j] = 0.f;

    for (int c0 = 0; c0 < INNER; c0 += 32) {
        int h = c0 >> 5;
        __syncthreads();
        {   // W tile [o][c] hi/lo
            int orow = t >> 1, cpart = (t & 1) * 16;
            const float4* s4 = (const float4*)(W + (size_t)(o0 + orow) * INNER + c0 + cpart);
#pragma unroll
            for (int j = 0; j < 4; j++) {
                float4 v = s4[j];
                int cidx = cpart + j * 4;
                float vh, vl;
                split_tf32(v.x, vh, vl); sWhi[orow * 36 + cidx + 0] = vh; sWlo[orow * 36 + cidx + 0] = vl;
                split_tf32(v.y, vh, vl); sWhi[orow * 36 + cidx + 1] = vh; sWlo[orow * 36 + cidx + 1] = vl;
                split_tf32(v.z, vh, vl); sWhi[orow * 36 + cidx + 2] = vh; sWlo[orow * 36 + cidx + 2] = vl;
                split_tf32(v.w, vh, vl); sWhi[orow * 36 + cidx + 3] = vh; sWlo[orow * 36 + cidx + 3] = vl;
            }
        }
        {   // O tile: token-major, head h, hi/lo
            const float* gO = g_O + ((size_t)(b * NHEADS + h) * NN + n0) * DHD;
            int tok = t >> 1, dq = (t & 1) * 16;
            const float4* s4 = (const float4*)(gO + (size_t)tok * DHD + dq);
#pragma unroll
            for (int j = 0; j < 4; j++) {
                float4 v = s4[j];
                int didx = dq + j * 4;
                float vh, vl;
                split_tf32(v.x, vh, vl); sXhi[tok * 36 + didx + 0] = vh; sXlo[tok * 36 + didx + 0] = vl;
                split_tf32(v.y, vh, vl); sXhi[tok * 36 + didx + 1] = vh; sXlo[tok * 36 + didx + 1] = vl;
                split_tf32(v.z, vh, vl); sXhi[tok * 36 + didx + 2] = vh; sXlo[tok * 36 + didx + 2] = vl;
                split_tf32(v.w, vh, vl); sXhi[tok * 36 + didx + 3] = vh; sXlo[tok * 36 + didx + 3] = vl;
            }
        }
        __syncthreads();
#pragma unroll
        for (int kc = 0; kc < 4; kc++) {
            int k0 = kc * 8;
            unsigned ah0 = __float_as_uint(sWhi[(q0 + g) * 36 + k0 + tg]);
            unsigned ah1 = __float_as_uint(sWhi[(q0 + g + 8) * 36 + k0 + tg]);
            unsigned ah2 = __float_as_uint(sWhi[(q0 + g) * 36 + k0 + tg + 4]);
            unsigned ah3 = __float_as_uint(sWhi[(q0 + g + 8) * 36 + k0 + tg + 4]);
            unsigned al0 = __float_as_uint(sWlo[(q0 + g) * 36 + k0 + tg]);
            unsigned al1 = __float_as_uint(sWlo[(q0 + g + 8) * 36 + k0 + tg]);
            unsigned al2 = __float_as_uint(sWlo[(q0 + g) * 36 + k0 + tg + 4]);
            unsigned al3 = __float_as_uint(sWlo[(q0 + g + 8) * 36 + k0 + tg + 4]);
#pragma unroll
            for (int nt = 0; nt < 16; nt++) {
                unsigned bh0 = __float_as_uint(sXhi[(nt * 8 + g) * 36 + k0 + tg]);
                unsigned bh1 = __float_as_uint(sXhi[(nt * 8 + g) * 36 + k0 + tg + 4]);
                unsigned bl0 = __float_as_uint(sXlo[(nt * 8 + g) * 36 + k0 + tg]);
                unsigned bl1 = __float_as_uint(sXlo[(nt * 8 + g) * 36 + k0 + tg + 4]);
                MMA_TF32(c[nt][0], c[nt][1], c[nt][2], c[nt][3], ah0, ah1, ah2, ah3, bh0, bh1);
                MMA_TF32(c[nt][0], c[nt][1], c[nt][2], c[nt][3], ah0, ah1, ah2, ah3, bl0, bl1);
                MMA_TF32(c[nt][0], c[nt][1], c[nt][2], c[nt][3], al0, al1, al2, al3, bh0, bh1);
            }
        }
    }

    int oA = o0 + q0 + g, oB = oA + 8;
    float bbA = __ldg(&wb[oA]), bbB = __ldg(&wb[oB]);
#pragma unroll
    for (int nt = 0; nt < 16; nt++) {
        int n = n0 + nt * 8 + 2 * tg;
        *(float2*)(out + (size_t)oA * NN + n) = make_float2(c[nt][0] + bbA, c[nt][1] + bbA);
        *(float2*)(out + (size_t)oB * NN + n) = make_float2(c[nt][2] + bbB, c[nt][3] + bbB);
    }
}

// ---------------- launch ----------------
extern "C" void kernel_launch(void* const* d_in, const int* in_sizes, int n_in,
                              void* d_out, int out_size) {
    const float* x      = (const float*)d_in[0];
    const float* rgb    = (const float*)d_in[1];
    const float* wq     = (const float*)d_in[2];
    const float* bq     = (const float*)d_in[3];
    const float* wk     = (const float*)d_in[4];
    const float* bk     = (const float*)d_in[5];
    const float* wv     = (const float*)d_in[6];
    const float* bv     = (const float*)d_in[7];
    const float* wproj  = (const float*)d_in[8];
    const float* bproj  = (const float*)d_in[9];
    const float* c1_w   = (const float*)d_in[10];
    const float* c1_b   = (const float*)d_in[11];
    const float* c2_w   = (const float*)d_in[12];
    const float* c2_b   = (const float*)d_in[13];
    const float* gq_w   = (const float*)d_in[14];
    const float* gq_b   = (const float*)d_in[15];
    const float* bqf_w  = (const float*)d_in[16];
    const float* bqf_b  = (const float*)d_in[17];
    const float* gk_w   = (const float*)d_in[18];
    const float* gk_b   = (const float*)d_in[19];
    const float* bkf_w  = (const float*)d_in[20];
    const float* bkf_b  = (const float*)d_in[21];
    const float* gv_w   = (const float*)d_in[22];
    const float* gv_b   = (const float*)d_in[23];
    const float* bvf_w  = (const float*)d_in[24];
    const float* bvf_b  = (const float*)d_in[25];
    const float* alpha  = (const float*)d_in[26];

    luma_kernel<<<BB, 256>>>(rgb, alpha);
    conv1_kernel<<<dim3(8, BB), 256>>>(c1_w, c1_b);
    conv2_kernel<<<dim3(32, BB), 256>>>(c2_w, c2_b);
    film_kernel<<<dim3(6, BB), 256>>>(gq_w, gq_b, bqf_w, bqf_b, gk_w, gk_b, bkf_w, bkf_b,
                                      gv_w, gv_b, bvf_w, bvf_b);

    const int QKV_SMEM = 4 * 128 * 36 * 4;   // 73,728 B
    cudaFuncSetAttribute(qkv_kernel, cudaFuncAttributeMaxDynamicSharedMemorySize, QKV_SMEM);
    qkv_kernel<<<dim3(18, 2, 12), 256, QKV_SMEM>>>(x, wq, bq, wk, bk, wv, bv);

    const int ATTN_SMEM = (128 * QP * 2 + 128 * VP + 128 * PP + 128) * 4;  // 125,440 B
    cudaFuncSetAttribute(attn_kernel, cudaFuncAttributeMaxDynamicSharedMemorySize, ATTN_SMEM);
    attn_kernel<<<dim3(18, 32), 256, ATTN_SMEM>>>();

    const int PROJ_SMEM = 4 * 128 * 36 * 4;  // 73,728 B
    cudaFuncSetAttribute(proj_kernel, cudaFuncAttributeMaxDynamicSharedMemorySize, PROJ_SMEM);
    proj_kernel<<<dim3(18, 2, 4), 256, PROJ_SMEM>>>(wproj, bproj, (float*)d_out);
}